// round 15
// baseline (speedup 1.0000x reference)
#include <cuda_runtime.h>
#include <cuda_bf16.h>
#include <cuda_fp16.h>
#include <math.h>

#define NQ   5000
#define NS   10000
#define KNB  16
#define EPSF 1e-6f
#define BNEPS 1e-5f
#define NK   80000
#define SCB  625   // score kernel blocks

typedef unsigned long long u64;
typedef unsigned int u32;

// ---------------- fast-math helpers ----------------
__device__ __forceinline__ float sqa(float x){ float r; asm("sqrt.approx.f32 %0, %1;" : "=f"(r) : "f"(x)); return r; }
__device__ __forceinline__ float rcpa(float x){ float r; asm("rcp.approx.f32 %0, %1;" : "=f"(r) : "f"(x)); return r; }
__device__ __forceinline__ float rsqa(float x){ float r; asm("rsqrt.approx.f32 %0, %1;" : "=f"(r) : "f"(x)); return r; }
__device__ __forceinline__ u64 dup2(float x){
    u64 r; unsigned b = __float_as_uint(x);
    asm("mov.b64 %0, {%1, %1};" : "=l"(r) : "r"(b)); return r;
}
__device__ __forceinline__ void fma2(u64 &acc, u64 a, u64 b){
    asm("fma.rn.f32x2 %0, %1, %2, %0;" : "+l"(acc) : "l"(a), "l"(b));
}
__device__ __forceinline__ void cp16(void* smem, const void* gmem){
    u32 s = (u32)__cvta_generic_to_shared(smem);
    asm volatile("cp.async.cg.shared.global [%0], [%1], 16;" :: "r"(s), "l"(gmem));
}
__device__ __forceinline__ void cp16p(void* smem, const void* gmem, bool pred){
    u32 s = (u32)__cvta_generic_to_shared(smem);
    int sz = pred ? 16 : 0;
    asm volatile("cp.async.cg.shared.global [%0], [%1], 16, %2;" :: "r"(s), "l"(gmem), "r"(sz));
}

// ---------------- scratch ----------------
__device__ float g_stat1[32];
__device__ float g_stat2[16];
__device__ float g_stat3[256];
__device__ int g_barcnt[2];
__device__ volatile int g_barflag[2];
__device__ __align__(256) float g_scw[8*NK];
__device__ __align__(256) __half g_Apack[NS*3*128];   // fp16 A, [row][c]
__device__ __align__(256) __half g_WtG [512*128];     // fp16 W^T, permuted rows fp=h*8+g
__device__ __align__(256) __half g_WtBI[640*128];     // first 512 rows permuted
__device__ __align__(256) float g_W23[64*256];
__device__ __align__(256) __half g_Gh [NS*3*512];     // G fp16, cols fp = h*8+g
__device__ __align__(256) float g_BqId[NQ*3*640];     // cols<512: fp perm; 512+: identify
__device__ __align__(256) float g_f2 [NQ*3*64];
__device__ __align__(256) float g_pd3[NQ*3*256];

// ---------------- init ----------------
__global__ void k_init() {
    int t = threadIdx.x;
    if (t < 32)  g_stat1[t] = 0.f;
    if (t < 16)  g_stat2[t] = 0.f;
    if (t < 256) g_stat3[t] = 0.f;
    if (t < 2) { g_barcnt[t] = 0; g_barflag[t] = 0; }
}

// ---------------- prep A: coalesced transpose via smem, fp16 ----------------
__global__ void __launch_bounds__(256) k_prepA(const float* __restrict__ sf)
{
    __shared__ float sj[3072];
    int tid = threadIdx.x;
    int j0 = blockIdx.x * 8;
    #pragma unroll
    for (int e = tid; e < 3072; e += 256) sj[e] = sf[j0*384 + e];
    __syncthreads();
    #pragma unroll
    for (int e = tid; e < 3072; e += 256) {
        int jl = e / 384, rem = e - jl*384, d = rem >> 7, c = rem & 127;
        float v = sj[jl*384 + c*3 + d];
        int row = (j0 + jl)*3 + d;
        g_Apack[row*128 + c] = __float2half_rn(v);
    }
}

// ---------------- prep W ----------------
__global__ void k_prepW(const float* __restrict__ wb, const float* __restrict__ Wsc,
                        const float* __restrict__ unWf, const float* __restrict__ unWd)
{
    int e = blockIdx.x*256 + threadIdx.x;
    if (e < 65536) {
        int f = e >> 7, c = e & 127;
        int fs = (f & 7)*64 + (f >> 3);
        float v = wb[c*512+fs] + wb[(c+128)*512+fs];
        g_WtG[f*128 + c] = __float2half_rn(v);
    } else if (e < 147456) {
        int t = e - 65536; int f = t >> 7, c = t & 127;
        int fs = (f < 512) ? (f & 7)*64 + (f >> 3) : f;
        float v = (fs < 512) ? wb[c*512+fs] : Wsc[(fs-512)*128 + c];
        g_WtBI[f*128 + c] = __float2half_rn(v);
    } else if (e < 163840) {
        int t = e - 147456; int c = t >> 8, f = t & 255;
        g_W23[t] = (f < 128) ? unWf[f*64 + c] : unWd[(f-128)*64 + c];
    }
}

// ---------------- grid barrier (persistent-resident blocks only) ----------------
__device__ __forceinline__ void gridbar(int idx)
{
    __syncthreads();
    if (threadIdx.x == 0) {
        __threadfence();
        int t = atomicAdd(&g_barcnt[idx], 1);
        if (t == SCB - 1) { __threadfence(); g_barflag[idx] = 1; }
        else { while (g_barflag[idx] == 0) { } }
    }
    __syncthreads();
}

// ---------------- fused score network (1 kernel, 2 grid barriers) ----------------
__global__ void __launch_bounds__(128) k_scoreF(
    const float* __restrict__ q_pts, const float* __restrict__ s_pts,
    const int* __restrict__ nbr,
    const float* __restrict__ Wf, const float* __restrict__ Wd,
    const float* __restrict__ vng, const float* __restrict__ vnb,
    const float* __restrict__ W1,
    const float* __restrict__ bn1g, const float* __restrict__ bn1b,
    const float* __restrict__ W2, const float* __restrict__ b2)
{
    __shared__ float sWf[48], sWd[48], sW1[128], sW2[64];
    __shared__ float sG[16], sB[16], sM[16], sR[16];
    __shared__ float s3M[8], s3R[8], s3G[8], s3B[8], sb2[8];
    __shared__ float sacc[32];
    int tid = threadIdx.x;
    if (tid < 48) { sWf[tid] = Wf[tid]; sWd[tid] = Wd[tid]; }
    if (tid < 128) sW1[tid] = W1[tid];
    if (tid < 64) sW2[tid] = W2[tid];
    if (tid < 16) { sG[tid] = vng[tid]; sB[tid] = vnb[tid]; }
    if (tid < 8) { s3G[tid] = bn1g[tid]; s3B[tid] = bn1b[tid]; sb2[tid] = b2[tid]; }
    if (tid < 32) sacc[tid] = 0.f;
    __syncthreads();

    int n = blockIdx.x * 8 + (tid >> 4);
    int k = tid & 15;
    int idx = n*KNB + k;

    // geometry (kept in registers across all phases)
    int j = nbr[idx];
    float px = s_pts[j*3]   - q_pts[n*3];
    float py = s_pts[j*3+1] - q_pts[n*3+1];
    float pz = s_pts[j*3+2] - q_pts[n*3+2];
    float cx = px, cy = py, cz = pz;
    #pragma unroll
    for (int m = 8; m; m >>= 1) {
        cx += __shfl_xor_sync(0xffffffffu, cx, m, 16);
        cy += __shfl_xor_sync(0xffffffffu, cy, m, 16);
        cz += __shfl_xor_sync(0xffffffffu, cz, m, 16);
    }
    cx *= 0.0625f; cy *= 0.0625f; cz *= 0.0625f;
    float rx = py*cz - pz*cy, ry = pz*cx - px*cz, rz = px*cy - py*cx;

    // ---- phase 1: norm stats ----
    #pragma unroll
    for (int o = 0; o < 16; o++) {
        float w0 = sWf[3*o], w1 = sWf[3*o+1], w2 = sWf[3*o+2];
        float ax = w0*px + w1*cx + w2*rx;
        float ay = w0*py + w1*cy + w2*ry;
        float az = w0*pz + w1*cz + w2*rz;
        float nm = sqa(ax*ax + ay*ay + az*az) + EPSF;
        float s = nm, q = nm*nm;
        #pragma unroll
        for (int m = 16; m; m >>= 1) {
            s += __shfl_xor_sync(0xffffffffu, s, m);
            q += __shfl_xor_sync(0xffffffffu, q, m);
        }
        if ((tid & 31) == 0) { atomicAdd(&sacc[o], s); atomicAdd(&sacc[16+o], q); }
    }
    __syncthreads();
    if (tid < 32) atomicAdd(&g_stat1[tid], sacc[tid]);

    gridbar(0);

    if (tid < 16) {
        volatile float* vs = g_stat1;
        float m = vs[tid] * 1.25e-5f;
        float v = vs[16+tid] * 1.25e-5f - m*m;
        sM[tid] = m; sR[tid] = rsqa(v + BNEPS);
    }
    if (tid < 16) sacc[tid] = 0.f;
    __syncthreads();

    // ---- phase 2: bn + act + W1 (reuse register geometry) ----
    float s0[16];
    #pragma unroll
    for (int o = 0; o < 16; o++) {
        float w0 = sWf[3*o], w1 = sWf[3*o+1], w2 = sWf[3*o+2];
        float ax = w0*px + w1*cx + w2*rx;
        float ay = w0*py + w1*cy + w2*ry;
        float az = w0*pz + w1*cz + w2*rz;
        float nm = sqa(ax*ax + ay*ay + az*az) + EPSF;
        float scl = (sG[o]*(nm - sM[o])*sR[o] + sB[o]) * rcpa(nm);
        ax *= scl; ay *= scl; az *= scl;
        float u0 = sWd[3*o], u1 = sWd[3*o+1], u2 = sWd[3*o+2];
        float dx = u0*px + u1*cx + u2*rx;
        float dy = u0*py + u1*cy + u2*ry;
        float dz = u0*pz + u1*cz + u2*rz;
        float dot = ax*dx + ay*dy + az*dz;
        float dsq = dx*dx + dy*dy + dz*dz;
        float t = dot * rcpa(dsq + EPSF);
        float ex, ey, ez;
        if (dot >= 0.f) { ex = ax; ey = ay; ez = az; }
        else { ex = ax - t*dx; ey = ay - t*dy; ez = az - t*dz; }
        ex = 0.2f*ax + 0.8f*ex; ey = 0.2f*ay + 0.8f*ey; ez = 0.2f*az + 0.8f*ez;
        s0[o] = sqa(ex*ex + ey*ey + ez*ez);
    }
    float v1[8];
    #pragma unroll
    for (int c = 0; c < 8; c++) {
        float v = 0.f;
        #pragma unroll
        for (int o = 0; o < 16; o++) v += sW1[c*16+o] * s0[o];
        v1[c] = v;
        float s = v, q = v*v;
        #pragma unroll
        for (int m = 16; m; m >>= 1) {
            s += __shfl_xor_sync(0xffffffffu, s, m);
            q += __shfl_xor_sync(0xffffffffu, q, m);
        }
        if ((tid & 31) == 0) { atomicAdd(&sacc[c], s); atomicAdd(&sacc[8+c], q); }
    }
    __syncthreads();
    if (tid < 16) atomicAdd(&g_stat2[tid], sacc[tid]);

    gridbar(1);

    if (tid < 8) {
        volatile float* vs = g_stat2;
        float m = vs[tid] * 1.25e-5f;
        float v = vs[8+tid] * 1.25e-5f - m*m;
        s3M[tid] = m; s3R[tid] = rsqa(v + BNEPS);
    }
    __syncthreads();

    // ---- phase 3: bn1 + relu + W2 + softmax (register-held v1) ----
    float s[8];
    #pragma unroll
    for (int c = 0; c < 8; c++) {
        float v = s3G[c]*(v1[c] - s3M[c])*s3R[c] + s3B[c];
        s[c] = v > 0.f ? v : 0.f;
    }
    float t[8]; float mx = -1e30f;
    #pragma unroll
    for (int c3 = 0; c3 < 8; c3++) {
        float v = sb2[c3];
        #pragma unroll
        for (int c = 0; c < 8; c++) v += sW2[c3*8+c] * s[c];
        t[c3] = v; mx = fmaxf(mx, v);
    }
    float sum = 0.f;
    #pragma unroll
    for (int c3 = 0; c3 < 8; c3++) { t[c3] = __expf(t[c3]-mx); sum += t[c3]; }
    float inv = rcpa(sum);
    #pragma unroll
    for (int c3 = 0; c3 < 8; c3++) g_scw[c3*NK + idx] = t[c3]*inv;
}

// ---------------- tensor-core GEMM (fp16, K=128, cp.async pipelined) ----------------
__global__ void __launch_bounds__(256,2) k_gemmt(
    const int* __restrict__ rowmap, int wsel, int csel, int M, int Nc)
{
    const __half* Ap = g_Apack;
    const __half* Wt = (wsel == 0) ? g_WtG : g_WtBI;

    __shared__ __align__(16) __half As[2][128][40];
    __shared__ __align__(16) __half Bs[2][128][40];

    int tid = threadIdx.x;
    int bm = blockIdx.x * 128, bn = blockIdx.y * 128;

    int lr = tid >> 2;
    int lc8 = (tid & 3) * 8;

    const __half *pa0, *pa1; bool gd0, gd1;
    {
        int r = bm + lr; gd0 = r < M;
        int src = gd0 ? r : 0;
        if (rowmap && gd0) { int grp = r/3, d = r - grp*3; src = rowmap[grp*16]*3 + d; }
        pa0 = Ap + (size_t)src*128;
        r = bm + lr + 64; gd1 = r < M;
        src = gd1 ? r : 0;
        if (rowmap && gd1) { int grp = r/3, d = r - grp*3; src = rowmap[grp*16]*3 + d; }
        pa1 = Ap + (size_t)src*128;
    }
    const __half* pb0 = Wt + (size_t)(bn + lr)*128 + lc8;
    const __half* pb1 = Wt + (size_t)(bn + lr + 64)*128 + lc8;

    int lane = tid & 31, wid = tid >> 5;
    int warp_m = (wid & 1) * 64;
    int warp_n = (wid >> 1) * 32;

    float acc[4][4][4] = {};

    auto issue = [&](int kt, int b){
        int ktb = kt * 32;
        cp16p(&As[b][lr][lc8],    pa0 + ktb + lc8, gd0);
        cp16p(&As[b][lr+64][lc8], pa1 + ktb + lc8, gd1);
        cp16(&Bs[b][lr][lc8],    pb0 + ktb);
        cp16(&Bs[b][lr+64][lc8], pb1 + ktb);
        asm volatile("cp.async.commit_group;" ::: "memory");
    };

    issue(0, 0);
    asm volatile("cp.async.wait_group 0;" ::: "memory");
    __syncthreads();
    int buf = 0;

    #pragma unroll 1
    for (int kt = 0; kt < 4; kt++) {
        if (kt + 1 < 4) issue(kt + 1, buf ^ 1);
        #pragma unroll
        for (int ks = 0; ks < 32; ks += 16) {
            u32 af[4][4], bf2[4][2];
            #pragma unroll
            for (int mt = 0; mt < 4; mt++) {
                int row = warp_m + mt*16 + (lane & 7) + ((lane >> 3) & 1)*8;
                int col = ks + (lane >> 4)*8;
                u32 sa = (u32)__cvta_generic_to_shared(&As[buf][row][col]);
                asm volatile("ldmatrix.sync.aligned.m8n8.x4.shared.b16 {%0,%1,%2,%3}, [%4];"
                    : "=r"(af[mt][0]), "=r"(af[mt][1]), "=r"(af[mt][2]), "=r"(af[mt][3]) : "r"(sa));
            }
            #pragma unroll
            for (int pr = 0; pr < 2; pr++) {
                int row = warp_n + pr*16 + (lane & 7) + ((lane >> 4) & 1)*8;
                int col = ks + ((lane >> 3) & 1)*8;
                u32 sb = (u32)__cvta_generic_to_shared(&Bs[buf][row][col]);
                asm volatile("ldmatrix.sync.aligned.m8n8.x4.shared.b16 {%0,%1,%2,%3}, [%4];"
                    : "=r"(bf2[pr*2][0]), "=r"(bf2[pr*2][1]),
                      "=r"(bf2[pr*2+1][0]), "=r"(bf2[pr*2+1][1]) : "r"(sb));
            }
            #pragma unroll
            for (int mt = 0; mt < 4; mt++)
                #pragma unroll
                for (int nt = 0; nt < 4; nt++) {
                    asm volatile(
                        "mma.sync.aligned.m16n8k16.row.col.f32.f16.f16.f32 "
                        "{%0,%1,%2,%3}, {%4,%5,%6,%7}, {%8,%9}, {%0,%1,%2,%3};"
                        : "+f"(acc[mt][nt][0]), "+f"(acc[mt][nt][1]),
                          "+f"(acc[mt][nt][2]), "+f"(acc[mt][nt][3])
                        : "r"(af[mt][0]), "r"(af[mt][1]), "r"(af[mt][2]), "r"(af[mt][3]),
                          "r"(bf2[nt][0]), "r"(bf2[nt][1]));
                }
        }
        if (kt + 1 < 4) {
            asm volatile("cp.async.wait_group 0;" ::: "memory");
            __syncthreads();
            buf ^= 1;
        }
    }

    int g = lane >> 2, tig = lane & 3;
    #pragma unroll
    for (int mt = 0; mt < 4; mt++) {
        #pragma unroll
        for (int nt = 0; nt < 4; nt++) {
            int r0 = bm + warp_m + mt*16 + g;
            int cc = bn + warp_n + nt*8 + 2*tig;
            int r1 = r0 + 8;
            if (csel == 0) {
                if (r0 < M)
                    *(__half2*)&g_Gh[(size_t)r0*Nc + cc] = __floats2half2_rn(acc[mt][nt][0], acc[mt][nt][1]);
                if (r1 < M)
                    *(__half2*)&g_Gh[(size_t)r1*Nc + cc] = __floats2half2_rn(acc[mt][nt][2], acc[mt][nt][3]);
            } else {
                if (r0 < M)
                    *(float2*)&g_BqId[(size_t)r0*Nc + cc] = make_float2(acc[mt][nt][0], acc[mt][nt][1]);
                if (r1 < M)
                    *(float2*)&g_BqId[(size_t)r1*Nc + cc] = make_float2(acc[mt][nt][2], acc[mt][nt][3]);
            }
        }
    }
}

// ---------------- FFMA2 SGEMM (pd3 only) ----------------
#define GBM 128
#define GBN 128
#define GBK 16
__global__ void __launch_bounds__(256,2) k_gemm2(int M, int Nc, int Kd)
{
    const float* A = g_f2;
    const float* W = g_W23;
    float* C = g_pd3;

    __shared__ __align__(16) float As[2][GBK][GBM+4];
    __shared__ __align__(16) float Ws[2][GBK][GBN];
    int tid = threadIdx.x;
    int bm = blockIdx.x * GBM, bn = blockIdx.y * GBN;

    int ar = tid >> 2, ac = (tid & 3) * 4;
    const float *pa0, *pa1; bool gd0, gd1;
    {
        int r = bm + ar; gd0 = r < M;
        pa0 = A + (size_t)(gd0 ? r : 0)*Kd + ac;
        r = bm + ar + 64; gd1 = r < M;
        pa1 = A + (size_t)(gd1 ? r : 0)*Kd + ac;
    }
    int wr = tid >> 4, wc = (tid & 15) * 8;
    const float* pw = W + (size_t)wr*Nc + bn + wc;

    int tr = tid >> 4, tc = tid & 15;
    u64 acc2[8][4] = {};
    int nk = Kd / GBK;
    const float4 f4z = make_float4(0.f,0.f,0.f,0.f);

    float4 va0 = gd0 ? *(const float4*)(pa0) : f4z;
    float4 va1 = gd1 ? *(const float4*)(pa1) : f4z;
    float4 vb0 = *(const float4*)(pw);
    float4 vb1 = *(const float4*)(pw + 4);
    As[0][ac+0][ar] = va0.x; As[0][ac+1][ar] = va0.y; As[0][ac+2][ar] = va0.z; As[0][ac+3][ar] = va0.w;
    As[0][ac+0][ar+64] = va1.x; As[0][ac+1][ar+64] = va1.y; As[0][ac+2][ar+64] = va1.z; As[0][ac+3][ar+64] = va1.w;
    *(float4*)&Ws[0][wr][wc] = vb0; *(float4*)&Ws[0][wr][wc+4] = vb1;
    __syncthreads();
    int buf = 0;

    for (int kt = 0; kt < nk; kt++) {
        if (kt + 1 < nk) {
            int k0 = (kt+1) * GBK;
            va0 = gd0 ? *(const float4*)(pa0 + k0) : f4z;
            va1 = gd1 ? *(const float4*)(pa1 + k0) : f4z;
            vb0 = *(const float4*)(pw + (size_t)k0*Nc);
            vb1 = *(const float4*)(pw + (size_t)k0*Nc + 4);
        }
        #pragma unroll
        for (int kk = 0; kk < GBK; kk++) {
            float4 a0 = *(const float4*)&As[buf][kk][tr*8];
            float4 a1 = *(const float4*)&As[buf][kk][tr*8+4];
            ulonglong2 B0 = *(const ulonglong2*)&Ws[buf][kk][tc*8];
            ulonglong2 B1 = *(const ulonglong2*)&Ws[buf][kk][tc*8+4];
            float aa[8] = {a0.x,a0.y,a0.z,a0.w,a1.x,a1.y,a1.z,a1.w};
            #pragma unroll
            for (int ii = 0; ii < 8; ii++) {
                u64 ad = dup2(aa[ii]);
                fma2(acc2[ii][0], ad, B0.x);
                fma2(acc2[ii][1], ad, B0.y);
                fma2(acc2[ii][2], ad, B1.x);
                fma2(acc2[ii][3], ad, B1.y);
            }
        }
        if (kt + 1 < nk) {
            int nb = buf ^ 1;
            As[nb][ac+0][ar] = va0.x; As[nb][ac+1][ar] = va0.y; As[nb][ac+2][ar] = va0.z; As[nb][ac+3][ar] = va0.w;
            As[nb][ac+0][ar+64] = va1.x; As[nb][ac+1][ar+64] = va1.y; As[nb][ac+2][ar+64] = va1.z; As[nb][ac+3][ar+64] = va1.w;
            *(float4*)&Ws[nb][wr][wc] = vb0; *(float4*)&Ws[nb][wr][wc+4] = vb1;
            __syncthreads();
            buf = nb;
        }
    }
    #pragma unroll
    for (int i = 0; i < 8; i++) {
        int r = bm + tr*8 + i;
        if (r < M) {
            float* cp = &C[(size_t)r*Nc + bn + tc*8];
            *(ulonglong2*)cp     = make_ulonglong2(acc2[i][0], acc2[i][1]);
            *(ulonglong2*)(cp+4) = make_ulonglong2(acc2[i][2], acc2[i][3]);
        }
    }
}

// ---------------- combine + mid fused (vectorized G loads) ----------------
__global__ void __launch_bounds__(256) k_combine(const float* __restrict__ wb,
    const float* __restrict__ q_pts, const float* __restrict__ s_pts,
    const int* __restrict__ nbr, const float* __restrict__ Wr)
{
    __shared__ float sc[4][16][8];
    __shared__ int   jl[4][16];
    __shared__ float ptsh[4][16][3];
    __shared__ float Wsh[64][65];
    __shared__ float fsh[4][3][64];
    int tid = threadIdx.x;
    int base = blockIdx.x * 4;
    {
        int e = tid;
        int nl = e >> 6, rem = e & 63, k = rem >> 2, g0 = (rem & 3) * 2;
        int idx = (base+nl)*16 + k;
        sc[nl][k][g0]   = g_scw[g0*NK + idx];
        sc[nl][k][g0+1] = g_scw[(g0+1)*NK + idx];
    }
    if (tid < 64) jl[tid>>4][tid&15] = nbr[(base + (tid>>4))*16 + (tid&15)];
    if (tid < 192) {
        int nl = tid/48, rem = tid - nl*48, k = rem/3, d = rem - k*3;
        int n = base + nl;
        ptsh[nl][k][d] = s_pts[nbr[n*16+k]*3 + d] - q_pts[n*3 + d];
    }
    for (int e = tid; e < 4096; e += 256) {
        int o = e >> 6, hh = e & 63;
        Wsh[hh][o] = Wr[e];
    }
    int nl = tid >> 6, h = tid & 63;
    int n = base + nl;
    float bq[3][8], w2[8];
    #pragma unroll
    for (int g = 0; g < 8; g++) w2[g] = wb[256*512 + g*64 + h];
    #pragma unroll
    for (int d = 0; d < 3; d++) {
        float4 b0 = *(const float4*)&g_BqId[(size_t)(n*3+d)*640 + h*8];
        float4 b1 = *(const float4*)&g_BqId[(size_t)(n*3+d)*640 + h*8 + 4];
        bq[d][0]=b0.x; bq[d][1]=b0.y; bq[d][2]=b0.z; bq[d][3]=b0.w;
        bq[d][4]=b1.x; bq[d][5]=b1.y; bq[d][6]=b1.z; bq[d][7]=b1.w;
    }
    __syncthreads();
    float acc0 = 0.f, acc1 = 0.f, acc2 = 0.f;
    for (int k = 0; k < 16; k++) {
        int j = jl[nl][k];
        float s[8];
        #pragma unroll
        for (int g = 0; g < 8; g++) s[g] = sc[nl][k][g];
        float scw2 = 0.f;
        #pragma unroll
        for (int g = 0; g < 8; g++) scw2 += s[g]*w2[g];
        float v[3];
        #pragma unroll
        for (int d = 0; d < 3; d++) {
            uint4 gv = *(const uint4*)&g_Gh[(size_t)(j*3+d)*512 + h*8];
            __half2* gh = (__half2*)&gv;
            float2 q0 = __half22float2(gh[0]);
            float2 q1 = __half22float2(gh[1]);
            float2 q2 = __half22float2(gh[2]);
            float2 q3 = __half22float2(gh[3]);
            float t = s[0]*(q0.x - bq[d][0]) + s[1]*(q0.y - bq[d][1])
                    + s[2]*(q1.x - bq[d][2]) + s[3]*(q1.y - bq[d][3])
                    + s[4]*(q2.x - bq[d][4]) + s[5]*(q2.y - bq[d][5])
                    + s[6]*(q3.x - bq[d][6]) + s[7]*(q3.y - bq[d][7]);
            v[d] = t + ptsh[nl][k][d]*scw2;
        }
        float nrm2 = v[0]*v[0] + v[1]*v[1] + v[2]*v[2];
        float inv = rsqa(fmaxf(nrm2, 1e-24f));
        acc0 += v[0]*inv; acc1 += v[1]*inv; acc2 += v[2]*inv;
    }
    fsh[nl][0][h] = acc0 * 0.0625f;
    fsh[nl][1][h] = acc1 * 0.0625f;
    fsh[nl][2][h] = acc2 * 0.0625f;
    __syncthreads();
    int o = h;
    float p[3], d2[3];
    #pragma unroll
    for (int d = 0; d < 3; d++) {
        p[d] = fsh[nl][d][o];
        float t = 0.f;
        #pragma unroll 8
        for (int hh = 0; hh < 64; hh++) t += fsh[nl][d][hh]*Wsh[hh][o];
        d2[d] = t;
    }
    float dot = p[0]*d2[0] + p[1]*d2[1] + p[2]*d2[2];
    float dsq = d2[0]*d2[0] + d2[1]*d2[1] + d2[2]*d2[2];
    float t2 = dot * rcpa(dsq + EPSF);
    #pragma unroll
    for (int d = 0; d < 3; d++) {
        float s = (dot >= 0.f) ? p[d] : p[d] - t2*d2[d];
        g_f2[(n*3+d)*64 + o] = 0.2f*p[d] + 0.8f*s;
    }
}

// ---------------- stats of ||p3|| (grid-strided) ----------------
__global__ void k_stat3b()
{
    int o = threadIdx.x;
    float s = 0.f, ss = 0.f;
    for (int n = blockIdx.x; n < 5000; n += gridDim.x) {
        float a = g_pd3[(size_t)(n*3+0)*256 + o];
        float b = g_pd3[(size_t)(n*3+1)*256 + o];
        float c = g_pd3[(size_t)(n*3+2)*256 + o];
        float nm = sqa(a*a + b*b + c*c) + EPSF;
        s += nm; ss += nm*nm;
    }
    atomicAdd(&g_stat3[o], s);
    atomicAdd(&g_stat3[128+o], ss);
}

// ---------------- final: 2 n per block ----------------
__global__ void k_tail2(const float* __restrict__ ung, const float* __restrict__ unb,
                        float* __restrict__ out)
{
    int tid = threadIdx.x;
    int n = blockIdx.x * 2 + (tid >> 7);
    int o = tid & 127;
    float m = g_stat3[o] * 2e-4f;
    float v = g_stat3[128+o] * 2e-4f - m*m;
    float rstd = rsqa(v + BNEPS);
    float a0 = g_pd3[(size_t)(n*3+0)*256 + o];
    float a1 = g_pd3[(size_t)(n*3+1)*256 + o];
    float a2 = g_pd3[(size_t)(n*3+2)*256 + o];
    float nm = sqa(a0*a0 + a1*a1 + a2*a2) + EPSF;
    float scl = (ung[o]*(nm - m)*rstd + unb[o]) * rcpa(nm);
    a0 *= scl; a1 *= scl; a2 *= scl;
    float e0 = g_pd3[(size_t)(n*3+0)*256 + 128 + o];
    float e1 = g_pd3[(size_t)(n*3+1)*256 + 128 + o];
    float e2 = g_pd3[(size_t)(n*3+2)*256 + 128 + o];
    float dot = a0*e0 + a1*e1 + a2*e2;
    float dsq = e0*e0 + e1*e1 + e2*e2;
    float t = dot * rcpa(dsq + EPSF);
    float s0, s1, s2;
    if (dot >= 0.f) { s0 = a0; s1 = a1; s2 = a2; }
    else { s0 = a0 - t*e0; s1 = a1 - t*e1; s2 = a2 - t*e2; }
    float r0 = 0.2f*a0 + 0.8f*s0;
    float r1 = 0.2f*a1 + 0.8f*s1;
    float r2 = 0.2f*a2 + 0.8f*s2;
    int b = (n*128+o)*3;
    out[b]   = r0 + g_BqId[(size_t)(n*3+0)*640 + 512 + o];
    out[b+1] = r1 + g_BqId[(size_t)(n*3+1)*640 + 512 + o];
    out[b+2] = r2 + g_BqId[(size_t)(n*3+2)*640 + 512 + o];
}

// ---------------- launch (capture-safe fork/join) ----------------
extern "C" void kernel_launch(void* const* d_in, const int* in_sizes, int n_in,
                              void* d_out, int out_size)
{
    const float* q_pts  = (const float*)d_in[0];
    const float* s_pts  = (const float*)d_in[1];
    const float* s_feats= (const float*)d_in[2];
    const int*   nbr    = (const int*)  d_in[3];
    const float* Wf     = (const float*)d_in[4];
    const float* Wd     = (const float*)d_in[5];
    const float* vng    = (const float*)d_in[6];
    const float* vnb    = (const float*)d_in[7];
    const float* W1     = (const float*)d_in[8];
    const float* bn1g   = (const float*)d_in[9];
    const float* bn1b   = (const float*)d_in[10];
    const float* W2     = (const float*)d_in[11];
    const float* b2     = (const float*)d_in[12];
    const float* wb     = (const float*)d_in[13];
    const float* Wsc    = (const float*)d_in[14];
    const float* Wrelu  = (const float*)d_in[15];
    const float* unWf   = (const float*)d_in[16];
    const float* unWd   = (const float*)d_in[17];
    const float* ung    = (const float*)d_in[18];
    const float* unb    = (const float*)d_in[19];
    float* out = (float*)d_out;

    static cudaStream_t sB = nullptr, sC = nullptr;
    static cudaEvent_t evF = nullptr, evS = nullptr, evA = nullptr, evW = nullptr, evB = nullptr;
    if (!sB) {
        cudaStreamCreateWithFlags(&sB, cudaStreamNonBlocking);
        cudaStreamCreateWithFlags(&sC, cudaStreamNonBlocking);
        cudaEventCreateWithFlags(&evF, cudaEventDisableTiming);
        cudaEventCreateWithFlags(&evS, cudaEventDisableTiming);
        cudaEventCreateWithFlags(&evA, cudaEventDisableTiming);
        cudaEventCreateWithFlags(&evW, cudaEventDisableTiming);
        cudaEventCreateWithFlags(&evB, cudaEventDisableTiming);
    }

    // origin stream: init, then fork
    k_init<<<1, 256>>>();                                          // launch 1
    cudaEventRecord(evF, 0);

    // sC forks from origin: prepW concurrent with prepA
    cudaStreamWaitEvent(sC, evF, 0);
    k_prepW<<<640, 256, 0, sC>>>(wb, Wsc, unWf, unWd);             // launch 2
    cudaEventRecord(evW, sC);

    k_prepA<<<1250, 256>>>(s_feats);                               // launch 3
    cudaEventRecord(evA, 0);

    // G GEMM on origin (needs prepA + prepW)
    cudaStreamWaitEvent(0, evW, 0);
    k_gemmt<<<dim3(235, 4), 256>>>(nullptr, 0, 0, 30000, 512);     // launch 4 (profiled)

    // BqId GEMM on sC (after prepW same-stream; needs prepA via evA)
    cudaStreamWaitEvent(sC, evA, 0);
    k_gemmt<<<dim3(118, 5), 256, 0, sC>>>(nbr, 1, 1, 15000, 640);  // launch 5
    cudaEventRecord(evB, sC);

    // sB forks from origin: fused score kernel
    cudaStreamWaitEvent(sB, evF, 0);
    k_scoreF<<<SCB, 128, 0, sB>>>(q_pts, s_pts, nbr, Wf, Wd, vng, vnb, W1,
                                  bn1g, bn1b, W2, b2);
    cudaEventRecord(evS, sB);

    // join on origin
    cudaStreamWaitEvent(0, evS, 0);
    cudaStreamWaitEvent(0, evB, 0);

    k_combine<<<1250, 256>>>(wb, q_pts, s_pts, nbr, Wrelu);
    k_gemm2<<<dim3(118, 2), 256>>>(15000, 256, 64);
    k_stat3b<<<125, 128>>>();
    k_tail2<<<2500, 256>>>(ung, unb, out);
}

// round 16
// speedup vs baseline: 1.0229x; 1.0229x over previous
#include <cuda_runtime.h>
#include <cuda_bf16.h>
#include <cuda_fp16.h>
#include <math.h>

#define NQ   5000
#define NS   10000
#define KNB  16
#define EPSF 1e-6f
#define BNEPS 1e-5f
#define NK   80000

typedef unsigned long long u64;
typedef unsigned int u32;

// ---------------- fast-math helpers ----------------
__device__ __forceinline__ float sqa(float x){ float r; asm("sqrt.approx.f32 %0, %1;" : "=f"(r) : "f"(x)); return r; }
__device__ __forceinline__ float rcpa(float x){ float r; asm("rcp.approx.f32 %0, %1;" : "=f"(r) : "f"(x)); return r; }
__device__ __forceinline__ float rsqa(float x){ float r; asm("rsqrt.approx.f32 %0, %1;" : "=f"(r) : "f"(x)); return r; }
__device__ __forceinline__ u64 dup2(float x){
    u64 r; unsigned b = __float_as_uint(x);
    asm("mov.b64 %0, {%1, %1};" : "=l"(r) : "r"(b)); return r;
}
__device__ __forceinline__ void fma2(u64 &acc, u64 a, u64 b){
    asm("fma.rn.f32x2 %0, %1, %2, %0;" : "+l"(acc) : "l"(a), "l"(b));
}
__device__ __forceinline__ void cp16(void* smem, const void* gmem){
    u32 s = (u32)__cvta_generic_to_shared(smem);
    asm volatile("cp.async.cg.shared.global [%0], [%1], 16;" :: "r"(s), "l"(gmem));
}
__device__ __forceinline__ void cp16p(void* smem, const void* gmem, bool pred){
    u32 s = (u32)__cvta_generic_to_shared(smem);
    int sz = pred ? 16 : 0;
    asm volatile("cp.async.cg.shared.global [%0], [%1], 16, %2;" :: "r"(s), "l"(gmem), "r"(sz));
}

// ---------------- scratch ----------------
__device__ float g_stat1[32];
__device__ float g_stat2[16];
__device__ float g_stat3[256];
__device__ __align__(256) float g_s1[8*NK];
__device__ __align__(256) float g_scw[8*NK];
__device__ __align__(256) __half g_Apack[NS*3*128];   // fp16 A, [row][c]
__device__ __align__(256) __half g_WtG [512*128];     // fp16 W^T, permuted rows fp=h*8+g
__device__ __align__(256) __half g_WtBI[640*128];     // first 512 rows permuted
__device__ __align__(256) float g_W23[64*256];
__device__ __align__(256) __half g_Gh [NS*3*512];     // G fp16, cols fp = h*8+g
__device__ __align__(256) float g_BqId[NQ*3*640];     // cols<512: fp perm; 512+: identify
__device__ __align__(256) float g_f2 [NQ*3*64];
__device__ __align__(256) float g_pd3[NQ*3*256];

// ---------------- init ----------------
__global__ void k_init() {
    int t = threadIdx.x;
    if (t < 32)  g_stat1[t] = 0.f;
    if (t < 16)  g_stat2[t] = 0.f;
    if (t < 256) g_stat3[t] = 0.f;
}

// ---------------- prep A: coalesced transpose via smem, fp16 ----------------
__global__ void __launch_bounds__(256) k_prepA(const float* __restrict__ sf)
{
    __shared__ float sj[3072];
    int tid = threadIdx.x;
    int j0 = blockIdx.x * 8;
    #pragma unroll
    for (int e = tid; e < 3072; e += 256) sj[e] = sf[j0*384 + e];
    __syncthreads();
    #pragma unroll
    for (int e = tid; e < 3072; e += 256) {
        int jl = e / 384, rem = e - jl*384, d = rem >> 7, c = rem & 127;
        float v = sj[jl*384 + c*3 + d];
        int row = (j0 + jl)*3 + d;
        g_Apack[row*128 + c] = __float2half_rn(v);
    }
}

// ---------------- prep W: pack fp16 weights with column permutation ----------------
__global__ void k_prepW(const float* __restrict__ wb, const float* __restrict__ Wsc,
                        const float* __restrict__ unWf, const float* __restrict__ unWd)
{
    int e = blockIdx.x*256 + threadIdx.x;
    if (e < 65536) {
        int f = e >> 7, c = e & 127;
        int fs = (f & 7)*64 + (f >> 3);          // permutation: row fp holds old col
        float v = wb[c*512+fs] + wb[(c+128)*512+fs];
        g_WtG[f*128 + c] = __float2half_rn(v);
    } else if (e < 147456) {
        int t = e - 65536; int f = t >> 7, c = t & 127;
        int fs = (f < 512) ? (f & 7)*64 + (f >> 3) : f;
        float v = (fs < 512) ? wb[c*512+fs] : Wsc[(fs-512)*128 + c];
        g_WtBI[f*128 + c] = __float2half_rn(v);
    } else if (e < 163840) {
        int t = e - 147456; int c = t >> 8, f = t & 255;
        g_W23[t] = (f < 128) ? unWf[f*64 + c] : unWd[(f-128)*64 + c];
    }
}

// ---------------- shared geometry ----------------
__device__ __forceinline__ void geom(const float* q_pts, const float* s_pts,
    const int* nbr, int n, int k, float &px, float &py, float &pz,
    float &cx, float &cy, float &cz, float &rx, float &ry, float &rz)
{
    int j = nbr[n*KNB + k];
    px = s_pts[j*3]   - q_pts[n*3];
    py = s_pts[j*3+1] - q_pts[n*3+1];
    pz = s_pts[j*3+2] - q_pts[n*3+2];
    cx = px; cy = py; cz = pz;
    #pragma unroll
    for (int m = 8; m; m >>= 1) {
        cx += __shfl_xor_sync(0xffffffffu, cx, m, 16);
        cy += __shfl_xor_sync(0xffffffffu, cy, m, 16);
        cz += __shfl_xor_sync(0xffffffffu, cz, m, 16);
    }
    cx *= 0.0625f; cy *= 0.0625f; cz *= 0.0625f;
    rx = py*cz - pz*cy; ry = pz*cx - px*cz; rz = px*cy - py*cx;
}

// ---------------- score pass 1 ----------------
__global__ void k_score1(const float* __restrict__ q_pts, const float* __restrict__ s_pts,
                         const int* __restrict__ nbr, const float* __restrict__ Wf)
{
    __shared__ float sWf[48];
    __shared__ float sacc[32];
    int tid = threadIdx.x;
    if (tid < 48) sWf[tid] = Wf[tid];
    if (tid < 32) sacc[tid] = 0.f;
    __syncthreads();
    int n = blockIdx.x * 8 + (tid >> 4);
    int k = tid & 15;
    float px,py,pz,cx,cy,cz,rx,ry,rz;
    geom(q_pts, s_pts, nbr, n, k, px,py,pz,cx,cy,cz,rx,ry,rz);
    #pragma unroll
    for (int o = 0; o < 16; o++) {
        float w0 = sWf[3*o], w1 = sWf[3*o+1], w2 = sWf[3*o+2];
        float ax = w0*px + w1*cx + w2*rx;
        float ay = w0*py + w1*cy + w2*ry;
        float az = w0*pz + w1*cz + w2*rz;
        float nm = sqa(ax*ax + ay*ay + az*az) + EPSF;
        float s = nm, q = nm*nm;
        #pragma unroll
        for (int m = 16; m; m >>= 1) {
            s += __shfl_xor_sync(0xffffffffu, s, m);
            q += __shfl_xor_sync(0xffffffffu, q, m);
        }
        if ((tid & 31) == 0) { atomicAdd(&sacc[o], s); atomicAdd(&sacc[16+o], q); }
    }
    __syncthreads();
    if (tid < 32) atomicAdd(&g_stat1[tid], sacc[tid]);
}

// ---------------- score pass 2 ----------------
__global__ void k_score2(const float* __restrict__ q_pts, const float* __restrict__ s_pts,
                         const int* __restrict__ nbr,
                         const float* __restrict__ Wf, const float* __restrict__ Wd,
                         const float* __restrict__ vng, const float* __restrict__ vnb,
                         const float* __restrict__ W1)
{
    __shared__ float sWf[48], sWd[48], sG[16], sB[16], sM[16], sR[16], sW1[128], sacc[16];
    int tid = threadIdx.x;
    if (tid < 48) { sWf[tid] = Wf[tid]; sWd[tid] = Wd[tid]; }
    if (tid < 16) {
        sG[tid] = vng[tid]; sB[tid] = vnb[tid];
        float m = g_stat1[tid] * 1.25e-5f;
        float v = g_stat1[16+tid] * 1.25e-5f - m*m;
        sM[tid] = m; sR[tid] = rsqa(v + BNEPS);
        sacc[tid] = 0.f;
    }
    if (tid < 128) sW1[tid] = W1[tid];
    __syncthreads();
    int n = blockIdx.x * 8 + (tid >> 4);
    int k = tid & 15;
    int idx = n*KNB + k;
    float px,py,pz,cx,cy,cz,rx,ry,rz;
    geom(q_pts, s_pts, nbr, n, k, px,py,pz,cx,cy,cz,rx,ry,rz);
    float s0[16];
    #pragma unroll
    for (int o = 0; o < 16; o++) {
        float w0 = sWf[3*o], w1 = sWf[3*o+1], w2 = sWf[3*o+2];
        float ax = w0*px + w1*cx + w2*rx;
        float ay = w0*py + w1*cy + w2*ry;
        float az = w0*pz + w1*cz + w2*rz;
        float nm = sqa(ax*ax + ay*ay + az*az) + EPSF;
        float scl = (sG[o]*(nm - sM[o])*sR[o] + sB[o]) * rcpa(nm);
        ax *= scl; ay *= scl; az *= scl;
        float u0 = sWd[3*o], u1 = sWd[3*o+1], u2 = sWd[3*o+2];
        float dx = u0*px + u1*cx + u2*rx;
        float dy = u0*py + u1*cy + u2*ry;
        float dz = u0*pz + u1*cz + u2*rz;
        float dot = ax*dx + ay*dy + az*dz;
        float dsq = dx*dx + dy*dy + dz*dz;
        float t = dot * rcpa(dsq + EPSF);
        float ex, ey, ez;
        if (dot >= 0.f) { ex = ax; ey = ay; ez = az; }
        else { ex = ax - t*dx; ey = ay - t*dy; ez = az - t*dz; }
        ex = 0.2f*ax + 0.8f*ex; ey = 0.2f*ay + 0.8f*ey; ez = 0.2f*az + 0.8f*ez;
        s0[o] = sqa(ex*ex + ey*ey + ez*ez);
    }
    #pragma unroll
    for (int c = 0; c < 8; c++) {
        float v = 0.f;
        #pragma unroll
        for (int o = 0; o < 16; o++) v += sW1[c*16+o] * s0[o];
        g_s1[c*NK + idx] = v;
        float s = v, q = v*v;
        #pragma unroll
        for (int m = 16; m; m >>= 1) {
            s += __shfl_xor_sync(0xffffffffu, s, m);
            q += __shfl_xor_sync(0xffffffffu, q, m);
        }
        if ((tid & 31) == 0) { atomicAdd(&sacc[c], s); atomicAdd(&sacc[8+c], q); }
    }
    __syncthreads();
    if (tid < 16) atomicAdd(&g_stat2[tid], sacc[tid]);
}

// ---------------- score pass 3 ----------------
__global__ void k_score3(const float* __restrict__ bn1g, const float* __restrict__ bn1b,
                         const float* __restrict__ W2, const float* __restrict__ b2)
{
    __shared__ float sM[8], sR[8], sG[8], sB[8], sW[64], sb[8];
    int tid = threadIdx.x;
    if (tid < 8) {
        float m = g_stat2[tid] * 1.25e-5f;
        float v = g_stat2[8+tid] * 1.25e-5f - m*m;
        sM[tid] = m; sR[tid] = rsqa(v + BNEPS);
        sG[tid] = bn1g[tid]; sB[tid] = bn1b[tid]; sb[tid] = b2[tid];
    }
    if (tid < 64) sW[tid] = W2[tid];
    __syncthreads();
    int idx = blockIdx.x * 128 + tid;
    float s[8];
    #pragma unroll
    for (int c = 0; c < 8; c++) {
        float v = g_s1[c*NK + idx];
        v = sG[c]*(v - sM[c])*sR[c] + sB[c];
        s[c] = v > 0.f ? v : 0.f;
    }
    float t[8]; float mx = -1e30f;
    #pragma unroll
    for (int c3 = 0; c3 < 8; c3++) {
        float v = sb[c3];
        #pragma unroll
        for (int c = 0; c < 8; c++) v += sW[c3*8+c] * s[c];
        t[c3] = v; mx = fmaxf(mx, v);
    }
    float sum = 0.f;
    #pragma unroll
    for (int c3 = 0; c3 < 8; c3++) { t[c3] = __expf(t[c3]-mx); sum += t[c3]; }
    float inv = rcpa(sum);
    #pragma unroll
    for (int c3 = 0; c3 < 8; c3++) g_scw[c3*NK + idx] = t[c3]*inv;
}

// ---------------- tensor-core GEMM (fp16, K=128, cp.async pipelined) ----------------
__global__ void __launch_bounds__(256,2) k_gemmt(
    const int* __restrict__ rowmap, int wsel, int csel, int M, int Nc)
{
    const __half* Ap = g_Apack;
    const __half* Wt = (wsel == 0) ? g_WtG : g_WtBI;

    __shared__ __align__(16) __half As[2][128][40];
    __shared__ __align__(16) __half Bs[2][128][40];

    int tid = threadIdx.x;
    int bm = blockIdx.x * 128, bn = blockIdx.y * 128;

    int lr = tid >> 2;
    int lc8 = (tid & 3) * 8;

    const __half *pa0, *pa1; bool gd0, gd1;
    {
        int r = bm + lr; gd0 = r < M;
        int src = gd0 ? r : 0;
        if (rowmap && gd0) { int grp = r/3, d = r - grp*3; src = rowmap[grp*16]*3 + d; }
        pa0 = Ap + (size_t)src*128;
        r = bm + lr + 64; gd1 = r < M;
        src = gd1 ? r : 0;
        if (rowmap && gd1) { int grp = r/3, d = r - grp*3; src = rowmap[grp*16]*3 + d; }
        pa1 = Ap + (size_t)src*128;
    }
    const __half* pb0 = Wt + (size_t)(bn + lr)*128 + lc8;
    const __half* pb1 = Wt + (size_t)(bn + lr + 64)*128 + lc8;

    int lane = tid & 31, wid = tid >> 5;
    int warp_m = (wid & 1) * 64;
    int warp_n = (wid >> 1) * 32;

    float acc[4][4][4] = {};

    auto issue = [&](int kt, int b){
        int ktb = kt * 32;
        cp16p(&As[b][lr][lc8],    pa0 + ktb + lc8, gd0);
        cp16p(&As[b][lr+64][lc8], pa1 + ktb + lc8, gd1);
        cp16(&Bs[b][lr][lc8],    pb0 + ktb);
        cp16(&Bs[b][lr+64][lc8], pb1 + ktb);
        asm volatile("cp.async.commit_group;" ::: "memory");
    };

    issue(0, 0);
    asm volatile("cp.async.wait_group 0;" ::: "memory");
    __syncthreads();
    int buf = 0;

    #pragma unroll 1
    for (int kt = 0; kt < 4; kt++) {
        if (kt + 1 < 4) issue(kt + 1, buf ^ 1);
        #pragma unroll
        for (int ks = 0; ks < 32; ks += 16) {
            u32 af[4][4], bf2[4][2];
            #pragma unroll
            for (int mt = 0; mt < 4; mt++) {
                int row = warp_m + mt*16 + (lane & 7) + ((lane >> 3) & 1)*8;
                int col = ks + (lane >> 4)*8;
                u32 sa = (u32)__cvta_generic_to_shared(&As[buf][row][col]);
                asm volatile("ldmatrix.sync.aligned.m8n8.x4.shared.b16 {%0,%1,%2,%3}, [%4];"
                    : "=r"(af[mt][0]), "=r"(af[mt][1]), "=r"(af[mt][2]), "=r"(af[mt][3]) : "r"(sa));
            }
            #pragma unroll
            for (int pr = 0; pr < 2; pr++) {
                int row = warp_n + pr*16 + (lane & 7) + ((lane >> 4) & 1)*8;
                int col = ks + ((lane >> 3) & 1)*8;
                u32 sb = (u32)__cvta_generic_to_shared(&Bs[buf][row][col]);
                asm volatile("ldmatrix.sync.aligned.m8n8.x4.shared.b16 {%0,%1,%2,%3}, [%4];"
                    : "=r"(bf2[pr*2][0]), "=r"(bf2[pr*2][1]),
                      "=r"(bf2[pr*2+1][0]), "=r"(bf2[pr*2+1][1]) : "r"(sb));
            }
            #pragma unroll
            for (int mt = 0; mt < 4; mt++)
                #pragma unroll
                for (int nt = 0; nt < 4; nt++) {
                    asm volatile(
                        "mma.sync.aligned.m16n8k16.row.col.f32.f16.f16.f32 "
                        "{%0,%1,%2,%3}, {%4,%5,%6,%7}, {%8,%9}, {%0,%1,%2,%3};"
                        : "+f"(acc[mt][nt][0]), "+f"(acc[mt][nt][1]),
                          "+f"(acc[mt][nt][2]), "+f"(acc[mt][nt][3])
                        : "r"(af[mt][0]), "r"(af[mt][1]), "r"(af[mt][2]), "r"(af[mt][3]),
                          "r"(bf2[nt][0]), "r"(bf2[nt][1]));
                }
        }
        if (kt + 1 < 4) {
            asm volatile("cp.async.wait_group 0;" ::: "memory");
            __syncthreads();
            buf ^= 1;
        }
    }

    int g = lane >> 2, tig = lane & 3;
    #pragma unroll
    for (int mt = 0; mt < 4; mt++) {
        #pragma unroll
        for (int nt = 0; nt < 4; nt++) {
            int r0 = bm + warp_m + mt*16 + g;
            int cc = bn + warp_n + nt*8 + 2*tig;
            int r1 = r0 + 8;
            if (csel == 0) {
                if (r0 < M)
                    *(__half2*)&g_Gh[(size_t)r0*Nc + cc] = __floats2half2_rn(acc[mt][nt][0], acc[mt][nt][1]);
                if (r1 < M)
                    *(__half2*)&g_Gh[(size_t)r1*Nc + cc] = __floats2half2_rn(acc[mt][nt][2], acc[mt][nt][3]);
            } else {
                if (r0 < M)
                    *(float2*)&g_BqId[(size_t)r0*Nc + cc] = make_float2(acc[mt][nt][0], acc[mt][nt][1]);
                if (r1 < M)
                    *(float2*)&g_BqId[(size_t)r1*Nc + cc] = make_float2(acc[mt][nt][2], acc[mt][nt][3]);
            }
        }
    }
}

// ---------------- FFMA2 SGEMM (pd3 only) ----------------
#define GBM 128
#define GBN 128
#define GBK 16
__global__ void __launch_bounds__(256,2) k_gemm2(int M, int Nc, int Kd)
{
    const float* A = g_f2;
    const float* W = g_W23;
    float* C = g_pd3;

    __shared__ __align__(16) float As[2][GBK][GBM+4];
    __shared__ __align__(16) float Ws[2][GBK][GBN];
    int tid = threadIdx.x;
    int bm = blockIdx.x * GBM, bn = blockIdx.y * GBN;

    int ar = tid >> 2, ac = (tid & 3) * 4;
    const float *pa0, *pa1; bool gd0, gd1;
    {
        int r = bm + ar; gd0 = r < M;
        pa0 = A + (size_t)(gd0 ? r : 0)*Kd + ac;
        r = bm + ar + 64; gd1 = r < M;
        pa1 = A + (size_t)(gd1 ? r : 0)*Kd + ac;
    }
    int wr = tid >> 4, wc = (tid & 15) * 8;
    const float* pw = W + (size_t)wr*Nc + bn + wc;

    int tr = tid >> 4, tc = tid & 15;
    u64 acc2[8][4] = {};
    int nk = Kd / GBK;
    const float4 f4z = make_float4(0.f,0.f,0.f,0.f);

    float4 va0 = gd0 ? *(const float4*)(pa0) : f4z;
    float4 va1 = gd1 ? *(const float4*)(pa1) : f4z;
    float4 vb0 = *(const float4*)(pw);
    float4 vb1 = *(const float4*)(pw + 4);
    As[0][ac+0][ar] = va0.x; As[0][ac+1][ar] = va0.y; As[0][ac+2][ar] = va0.z; As[0][ac+3][ar] = va0.w;
    As[0][ac+0][ar+64] = va1.x; As[0][ac+1][ar+64] = va1.y; As[0][ac+2][ar+64] = va1.z; As[0][ac+3][ar+64] = va1.w;
    *(float4*)&Ws[0][wr][wc] = vb0; *(float4*)&Ws[0][wr][wc+4] = vb1;
    __syncthreads();
    int buf = 0;

    for (int kt = 0; kt < nk; kt++) {
        if (kt + 1 < nk) {
            int k0 = (kt+1) * GBK;
            va0 = gd0 ? *(const float4*)(pa0 + k0) : f4z;
            va1 = gd1 ? *(const float4*)(pa1 + k0) : f4z;
            vb0 = *(const float4*)(pw + (size_t)k0*Nc);
            vb1 = *(const float4*)(pw + (size_t)k0*Nc + 4);
        }
        #pragma unroll
        for (int kk = 0; kk < GBK; kk++) {
            float4 a0 = *(const float4*)&As[buf][kk][tr*8];
            float4 a1 = *(const float4*)&As[buf][kk][tr*8+4];
            ulonglong2 B0 = *(const ulonglong2*)&Ws[buf][kk][tc*8];
            ulonglong2 B1 = *(const ulonglong2*)&Ws[buf][kk][tc*8+4];
            float aa[8] = {a0.x,a0.y,a0.z,a0.w,a1.x,a1.y,a1.z,a1.w};
            #pragma unroll
            for (int ii = 0; ii < 8; ii++) {
                u64 ad = dup2(aa[ii]);
                fma2(acc2[ii][0], ad, B0.x);
                fma2(acc2[ii][1], ad, B0.y);
                fma2(acc2[ii][2], ad, B1.x);
                fma2(acc2[ii][3], ad, B1.y);
            }
        }
        if (kt + 1 < nk) {
            int nb = buf ^ 1;
            As[nb][ac+0][ar] = va0.x; As[nb][ac+1][ar] = va0.y; As[nb][ac+2][ar] = va0.z; As[nb][ac+3][ar] = va0.w;
            As[nb][ac+0][ar+64] = va1.x; As[nb][ac+1][ar+64] = va1.y; As[nb][ac+2][ar+64] = va1.z; As[nb][ac+3][ar+64] = va1.w;
            *(float4*)&Ws[nb][wr][wc] = vb0; *(float4*)&Ws[nb][wr][wc+4] = vb1;
            __syncthreads();
            buf = nb;
        }
    }
    #pragma unroll
    for (int i = 0; i < 8; i++) {
        int r = bm + tr*8 + i;
        if (r < M) {
            float* cp = &C[(size_t)r*Nc + bn + tc*8];
            *(ulonglong2*)cp     = make_ulonglong2(acc2[i][0], acc2[i][1]);
            *(ulonglong2*)(cp+4) = make_ulonglong2(acc2[i][2], acc2[i][3]);
        }
    }
}

// ---------------- combine + mid fused (vectorized G loads) ----------------
__global__ void __launch_bounds__(256) k_combine(const float* __restrict__ wb,
    const float* __restrict__ q_pts, const float* __restrict__ s_pts,
    const int* __restrict__ nbr, const float* __restrict__ Wr)
{
    __shared__ float sc[4][16][8];
    __shared__ int   jl[4][16];
    __shared__ float ptsh[4][16][3];
    __shared__ float Wsh[64][65];
    __shared__ float fsh[4][3][64];
    int tid = threadIdx.x;
    int base = blockIdx.x * 4;
    {
        int e = tid;
        int nl = e >> 6, rem = e & 63, k = rem >> 2, g0 = (rem & 3) * 2;
        int idx = (base+nl)*16 + k;
        sc[nl][k][g0]   = g_scw[g0*NK + idx];
        sc[nl][k][g0+1] = g_scw[(g0+1)*NK + idx];
    }
    if (tid < 64) jl[tid>>4][tid&15] = nbr[(base + (tid>>4))*16 + (tid&15)];
    if (tid < 192) {
        int nl = tid/48, rem = tid - nl*48, k = rem/3, d = rem - k*3;
        int n = base + nl;
        ptsh[nl][k][d] = s_pts[nbr[n*16+k]*3 + d] - q_pts[n*3 + d];
    }
    for (int e = tid; e < 4096; e += 256) {
        int o = e >> 6, hh = e & 63;
        Wsh[hh][o] = Wr[e];
    }
    int nl = tid >> 6, h = tid & 63;
    int n = base + nl;
    float bq[3][8], w2[8];
    #pragma unroll
    for (int g = 0; g < 8; g++) w2[g] = wb[256*512 + g*64 + h];
    #pragma unroll
    for (int d = 0; d < 3; d++) {
        float4 b0 = *(const float4*)&g_BqId[(size_t)(n*3+d)*640 + h*8];
        float4 b1 = *(const float4*)&g_BqId[(size_t)(n*3+d)*640 + h*8 + 4];
        bq[d][0]=b0.x; bq[d][1]=b0.y; bq[d][2]=b0.z; bq[d][3]=b0.w;
        bq[d][4]=b1.x; bq[d][5]=b1.y; bq[d][6]=b1.z; bq[d][7]=b1.w;
    }
    __syncthreads();
    float acc0 = 0.f, acc1 = 0.f, acc2 = 0.f;
    for (int k = 0; k < 16; k++) {
        int j = jl[nl][k];
        float s[8];
        #pragma unroll
        for (int g = 0; g < 8; g++) s[g] = sc[nl][k][g];
        float scw2 = 0.f;
        #pragma unroll
        for (int g = 0; g < 8; g++) scw2 += s[g]*w2[g];
        float v[3];
        #pragma unroll
        for (int d = 0; d < 3; d++) {
            uint4 gv = *(const uint4*)&g_Gh[(size_t)(j*3+d)*512 + h*8];
            __half2* gh = (__half2*)&gv;
            float2 q0 = __half22float2(gh[0]);
            float2 q1 = __half22float2(gh[1]);
            float2 q2 = __half22float2(gh[2]);
            float2 q3 = __half22float2(gh[3]);
            float t = s[0]*(q0.x - bq[d][0]) + s[1]*(q0.y - bq[d][1])
                    + s[2]*(q1.x - bq[d][2]) + s[3]*(q1.y - bq[d][3])
                    + s[4]*(q2.x - bq[d][4]) + s[5]*(q2.y - bq[d][5])
                    + s[6]*(q3.x - bq[d][6]) + s[7]*(q3.y - bq[d][7]);
            v[d] = t + ptsh[nl][k][d]*scw2;
        }
        float nrm2 = v[0]*v[0] + v[1]*v[1] + v[2]*v[2];
        float inv = rsqa(fmaxf(nrm2, 1e-24f));
        acc0 += v[0]*inv; acc1 += v[1]*inv; acc2 += v[2]*inv;
    }
    fsh[nl][0][h] = acc0 * 0.0625f;
    fsh[nl][1][h] = acc1 * 0.0625f;
    fsh[nl][2][h] = acc2 * 0.0625f;
    __syncthreads();
    int o = h;
    float p[3], d2[3];
    #pragma unroll
    for (int d = 0; d < 3; d++) {
        p[d] = fsh[nl][d][o];
        float t = 0.f;
        #pragma unroll 8
        for (int hh = 0; hh < 64; hh++) t += fsh[nl][d][hh]*Wsh[hh][o];
        d2[d] = t;
    }
    float dot = p[0]*d2[0] + p[1]*d2[1] + p[2]*d2[2];
    float dsq = d2[0]*d2[0] + d2[1]*d2[1] + d2[2]*d2[2];
    float t2 = dot * rcpa(dsq + EPSF);
    #pragma unroll
    for (int d = 0; d < 3; d++) {
        float s = (dot >= 0.f) ? p[d] : p[d] - t2*d2[d];
        g_f2[(n*3+d)*64 + o] = 0.2f*p[d] + 0.8f*s;
    }
}

// ---------------- stats of ||p3|| (grid-strided) ----------------
__global__ void k_stat3b()
{
    int o = threadIdx.x;
    float s = 0.f, ss = 0.f;
    for (int n = blockIdx.x; n < 5000; n += gridDim.x) {
        float a = g_pd3[(size_t)(n*3+0)*256 + o];
        float b = g_pd3[(size_t)(n*3+1)*256 + o];
        float c = g_pd3[(size_t)(n*3+2)*256 + o];
        float nm = sqa(a*a + b*b + c*c) + EPSF;
        s += nm; ss += nm*nm;
    }
    atomicAdd(&g_stat3[o], s);
    atomicAdd(&g_stat3[128+o], ss);
}

// ---------------- final: 2 n per block ----------------
__global__ void k_tail2(const float* __restrict__ ung, const float* __restrict__ unb,
                        float* __restrict__ out)
{
    int tid = threadIdx.x;
    int n = blockIdx.x * 2 + (tid >> 7);
    int o = tid & 127;
    float m = g_stat3[o] * 2e-4f;
    float v = g_stat3[128+o] * 2e-4f - m*m;
    float rstd = rsqa(v + BNEPS);
    float a0 = g_pd3[(size_t)(n*3+0)*256 + o];
    float a1 = g_pd3[(size_t)(n*3+1)*256 + o];
    float a2 = g_pd3[(size_t)(n*3+2)*256 + o];
    float nm = sqa(a0*a0 + a1*a1 + a2*a2) + EPSF;
    float scl = (ung[o]*(nm - m)*rstd + unb[o]) * rcpa(nm);
    a0 *= scl; a1 *= scl; a2 *= scl;
    float e0 = g_pd3[(size_t)(n*3+0)*256 + 128 + o];
    float e1 = g_pd3[(size_t)(n*3+1)*256 + 128 + o];
    float e2 = g_pd3[(size_t)(n*3+2)*256 + 128 + o];
    float dot = a0*e0 + a1*e1 + a2*e2;
    float dsq = e0*e0 + e1*e1 + e2*e2;
    float t = dot * rcpa(dsq + EPSF);
    float s0, s1, s2;
    if (dot >= 0.f) { s0 = a0; s1 = a1; s2 = a2; }
    else { s0 = a0 - t*e0; s1 = a1 - t*e1; s2 = a2 - t*e2; }
    float r0 = 0.2f*a0 + 0.8f*s0;
    float r1 = 0.2f*a1 + 0.8f*s1;
    float r2 = 0.2f*a2 + 0.8f*s2;
    int b = (n*128+o)*3;
    out[b]   = r0 + g_BqId[(size_t)(n*3+0)*640 + 512 + o];
    out[b+1] = r1 + g_BqId[(size_t)(n*3+1)*640 + 512 + o];
    out[b+2] = r2 + g_BqId[(size_t)(n*3+2)*640 + 512 + o];
}

// ---------------- launch (capture-safe fork/join, best-known topology) ----------------
extern "C" void kernel_launch(void* const* d_in, const int* in_sizes, int n_in,
                              void* d_out, int out_size)
{
    const float* q_pts  = (const float*)d_in[0];
    const float* s_pts  = (const float*)d_in[1];
    const float* s_feats= (const float*)d_in[2];
    const int*   nbr    = (const int*)  d_in[3];
    const float* Wf     = (const float*)d_in[4];
    const float* Wd     = (const float*)d_in[5];
    const float* vng    = (const float*)d_in[6];
    const float* vnb    = (const float*)d_in[7];
    const float* W1     = (const float*)d_in[8];
    const float* bn1g   = (const float*)d_in[9];
    const float* bn1b   = (const float*)d_in[10];
    const float* W2     = (const float*)d_in[11];
    const float* b2     = (const float*)d_in[12];
    const float* wb     = (const float*)d_in[13];
    const float* Wsc    = (const float*)d_in[14];
    const float* Wrelu  = (const float*)d_in[15];
    const float* unWf   = (const float*)d_in[16];
    const float* unWd   = (const float*)d_in[17];
    const float* ung    = (const float*)d_in[18];
    const float* unb    = (const float*)d_in[19];
    float* out = (float*)d_out;

    static cudaStream_t sB = nullptr, sC = nullptr;
    static cudaEvent_t evF = nullptr, evS = nullptr, evA = nullptr, evW = nullptr, evB = nullptr;
    if (!sB) {
        cudaStreamCreateWithFlags(&sB, cudaStreamNonBlocking);
        cudaStreamCreateWithFlags(&sC, cudaStreamNonBlocking);
        cudaEventCreateWithFlags(&evF, cudaEventDisableTiming);
        cudaEventCreateWithFlags(&evS, cudaEventDisableTiming);
        cudaEventCreateWithFlags(&evA, cudaEventDisableTiming);
        cudaEventCreateWithFlags(&evW, cudaEventDisableTiming);
        cudaEventCreateWithFlags(&evB, cudaEventDisableTiming);
    }

    // origin stream: init, then fork
    k_init<<<1, 256>>>();                                          // launch 1
    cudaEventRecord(evF, 0);

    // sC forks from origin: prepW concurrent with prepA
    cudaStreamWaitEvent(sC, evF, 0);
    k_prepW<<<640, 256, 0, sC>>>(wb, Wsc, unWf, unWd);             // launch 2
    cudaEventRecord(evW, sC);

    k_prepA<<<1250, 256>>>(s_feats);                               // launch 3
    cudaEventRecord(evA, 0);

    // G GEMM on origin (needs prepA + prepW)
    cudaStreamWaitEvent(0, evW, 0);
    k_gemmt<<<dim3(235, 4), 256>>>(nullptr, 0, 0, 30000, 512);     // launch 4 (profiled)

    // BqId GEMM on sC (after prepW same-stream; needs prepA via evA)
    cudaStreamWaitEvent(sC, evA, 0);
    k_gemmt<<<dim3(118, 5), 256, 0, sC>>>(nbr, 1, 1, 15000, 640);  // launch 5
    cudaEventRecord(evB, sC);

    // sB forks from origin: score chain
    cudaStreamWaitEvent(sB, evF, 0);
    k_score1<<<625, 128, 0, sB>>>(q_pts, s_pts, nbr, Wf);
    k_score2<<<625, 128, 0, sB>>>(q_pts, s_pts, nbr, Wf, Wd, vng, vnb, W1);
    k_score3<<<625, 128, 0, sB>>>(bn1g, bn1b, W2, b2);
    cudaEventRecord(evS, sB);

    // join on origin
    cudaStreamWaitEvent(0, evS, 0);
    cudaStreamWaitEvent(0, evB, 0);

    k_combine<<<1250, 256>>>(wb, q_pts, s_pts, nbr, Wrelu);
    k_gemm2<<<dim3(118, 2), 256>>>(15000, 256, 64);
    k_stat3b<<<125, 128>>>();
    k_tail2<<<2500, 256>>>(ung, unb, out);
}

// round 17
// speedup vs baseline: 1.0246x; 1.0017x over previous
#include <cuda_runtime.h>
#include <cuda_bf16.h>
#include <cuda_fp16.h>
#include <math.h>

#define NQ   5000
#define NS   10000
#define KNB  16
#define EPSF 1e-6f
#define BNEPS 1e-5f
#define NK   80000

typedef unsigned long long u64;
typedef unsigned int u32;

// ---------------- fast-math helpers ----------------
__device__ __forceinline__ float sqa(float x){ float r; asm("sqrt.approx.f32 %0, %1;" : "=f"(r) : "f"(x)); return r; }
__device__ __forceinline__ float rcpa(float x){ float r; asm("rcp.approx.f32 %0, %1;" : "=f"(r) : "f"(x)); return r; }
__device__ __forceinline__ float rsqa(float x){ float r; asm("rsqrt.approx.f32 %0, %1;" : "=f"(r) : "f"(x)); return r; }
__device__ __forceinline__ u64 dup2(float x){
    u64 r; unsigned b = __float_as_uint(x);
    asm("mov.b64 %0, {%1, %1};" : "=l"(r) : "r"(b)); return r;
}
__device__ __forceinline__ void fma2(u64 &acc, u64 a, u64 b){
    asm("fma.rn.f32x2 %0, %1, %2, %0;" : "+l"(acc) : "l"(a), "l"(b));
}
__device__ __forceinline__ void cp16(void* smem, const void* gmem){
    u32 s = (u32)__cvta_generic_to_shared(smem);
    asm volatile("cp.async.cg.shared.global [%0], [%1], 16;" :: "r"(s), "l"(gmem));
}
__device__ __forceinline__ void cp16p(void* smem, const void* gmem, bool pred){
    u32 s = (u32)__cvta_generic_to_shared(smem);
    int sz = pred ? 16 : 0;
    asm volatile("cp.async.cg.shared.global [%0], [%1], 16, %2;" :: "r"(s), "l"(gmem), "r"(sz));
}

// ---------------- scratch ----------------
__device__ float g_stat1[32];
__device__ float g_stat2[16];
__device__ float g_stat3[256];
__device__ __align__(256) float g_s1[8*NK];
__device__ __align__(256) float g_scw[8*NK];
__device__ __align__(256) __half g_Apack[NS*3*128];   // fp16 A, [row][c]
__device__ __align__(256) __half g_WtG [512*128];     // fp16 W^T, permuted rows fp=h*8+g
__device__ __align__(256) __half g_WtBI[640*128];     // first 512 rows permuted
__device__ __align__(256) float g_W23[64*256];
__device__ __align__(256) __half g_Gh [NS*3*512];     // G fp16, cols fp = h*8+g
__device__ __align__(256) float g_BqId[NQ*3*640];     // cols<512: fp perm; 512+: identify
__device__ __align__(256) float g_f2 [NQ*3*64];
__device__ __align__(256) float g_pd3[NQ*3*256];

// ---------------- init ----------------
__global__ void k_init() {
    int t = threadIdx.x;
    if (t < 32)  g_stat1[t] = 0.f;
    if (t < 16)  g_stat2[t] = 0.f;
    if (t < 256) g_stat3[t] = 0.f;
}

// ---------------- prep A: coalesced transpose via smem, fp16 ----------------
__global__ void __launch_bounds__(256) k_prepA(const float* __restrict__ sf)
{
    __shared__ float sj[3072];
    int tid = threadIdx.x;
    int j0 = blockIdx.x * 8;
    #pragma unroll
    for (int e = tid; e < 3072; e += 256) sj[e] = sf[j0*384 + e];
    __syncthreads();
    #pragma unroll
    for (int e = tid; e < 3072; e += 256) {
        int jl = e / 384, rem = e - jl*384, d = rem >> 7, c = rem & 127;
        float v = sj[jl*384 + c*3 + d];
        int row = (j0 + jl)*3 + d;
        g_Apack[row*128 + c] = __float2half_rn(v);
    }
}

// ---------------- prep W: pack fp16 weights with column permutation ----------------
__global__ void k_prepW(const float* __restrict__ wb, const float* __restrict__ Wsc,
                        const float* __restrict__ unWf, const float* __restrict__ unWd)
{
    int e = blockIdx.x*256 + threadIdx.x;
    if (e < 65536) {
        int f = e >> 7, c = e & 127;
        int fs = (f & 7)*64 + (f >> 3);          // permutation: row fp holds old col
        float v = wb[c*512+fs] + wb[(c+128)*512+fs];
        g_WtG[f*128 + c] = __float2half_rn(v);
    } else if (e < 147456) {
        int t = e - 65536; int f = t >> 7, c = t & 127;
        int fs = (f < 512) ? (f & 7)*64 + (f >> 3) : f;
        float v = (fs < 512) ? wb[c*512+fs] : Wsc[(fs-512)*128 + c];
        g_WtBI[f*128 + c] = __float2half_rn(v);
    } else if (e < 163840) {
        int t = e - 147456; int c = t >> 8, f = t & 255;
        g_W23[t] = (f < 128) ? unWf[f*64 + c] : unWd[(f-128)*64 + c];
    }
}

// ---------------- shared geometry ----------------
__device__ __forceinline__ void geom(const float* q_pts, const float* s_pts,
    const int* nbr, int n, int k, float &px, float &py, float &pz,
    float &cx, float &cy, float &cz, float &rx, float &ry, float &rz)
{
    int j = nbr[n*KNB + k];
    px = s_pts[j*3]   - q_pts[n*3];
    py = s_pts[j*3+1] - q_pts[n*3+1];
    pz = s_pts[j*3+2] - q_pts[n*3+2];
    cx = px; cy = py; cz = pz;
    #pragma unroll
    for (int m = 8; m; m >>= 1) {
        cx += __shfl_xor_sync(0xffffffffu, cx, m, 16);
        cy += __shfl_xor_sync(0xffffffffu, cy, m, 16);
        cz += __shfl_xor_sync(0xffffffffu, cz, m, 16);
    }
    cx *= 0.0625f; cy *= 0.0625f; cz *= 0.0625f;
    rx = py*cz - pz*cy; ry = pz*cx - px*cz; rz = px*cy - py*cx;
}

// ---------------- score pass 1 ----------------
__global__ void k_score1(const float* __restrict__ q_pts, const float* __restrict__ s_pts,
                         const int* __restrict__ nbr, const float* __restrict__ Wf)
{
    __shared__ float sWf[48];
    __shared__ float sacc[32];
    int tid = threadIdx.x;
    if (tid < 48) sWf[tid] = Wf[tid];
    if (tid < 32) sacc[tid] = 0.f;
    __syncthreads();
    int n = blockIdx.x * 8 + (tid >> 4);
    int k = tid & 15;
    float px,py,pz,cx,cy,cz,rx,ry,rz;
    geom(q_pts, s_pts, nbr, n, k, px,py,pz,cx,cy,cz,rx,ry,rz);
    #pragma unroll
    for (int o = 0; o < 16; o++) {
        float w0 = sWf[3*o], w1 = sWf[3*o+1], w2 = sWf[3*o+2];
        float ax = w0*px + w1*cx + w2*rx;
        float ay = w0*py + w1*cy + w2*ry;
        float az = w0*pz + w1*cz + w2*rz;
        float nm = sqa(ax*ax + ay*ay + az*az) + EPSF;
        float s = nm, q = nm*nm;
        #pragma unroll
        for (int m = 16; m; m >>= 1) {
            s += __shfl_xor_sync(0xffffffffu, s, m);
            q += __shfl_xor_sync(0xffffffffu, q, m);
        }
        if ((tid & 31) == 0) { atomicAdd(&sacc[o], s); atomicAdd(&sacc[16+o], q); }
    }
    __syncthreads();
    if (tid < 32) atomicAdd(&g_stat1[tid], sacc[tid]);
}

// ---------------- score pass 2 ----------------
__global__ void k_score2(const float* __restrict__ q_pts, const float* __restrict__ s_pts,
                         const int* __restrict__ nbr,
                         const float* __restrict__ Wf, const float* __restrict__ Wd,
                         const float* __restrict__ vng, const float* __restrict__ vnb,
                         const float* __restrict__ W1)
{
    __shared__ float sWf[48], sWd[48], sG[16], sB[16], sM[16], sR[16], sW1[128], sacc[16];
    int tid = threadIdx.x;
    if (tid < 48) { sWf[tid] = Wf[tid]; sWd[tid] = Wd[tid]; }
    if (tid < 16) {
        sG[tid] = vng[tid]; sB[tid] = vnb[tid];
        float m = g_stat1[tid] * 1.25e-5f;
        float v = g_stat1[16+tid] * 1.25e-5f - m*m;
        sM[tid] = m; sR[tid] = rsqa(v + BNEPS);
        sacc[tid] = 0.f;
    }
    if (tid < 128) sW1[tid] = W1[tid];
    __syncthreads();
    int n = blockIdx.x * 8 + (tid >> 4);
    int k = tid & 15;
    int idx = n*KNB + k;
    float px,py,pz,cx,cy,cz,rx,ry,rz;
    geom(q_pts, s_pts, nbr, n, k, px,py,pz,cx,cy,cz,rx,ry,rz);
    float s0[16];
    #pragma unroll
    for (int o = 0; o < 16; o++) {
        float w0 = sWf[3*o], w1 = sWf[3*o+1], w2 = sWf[3*o+2];
        float ax = w0*px + w1*cx + w2*rx;
        float ay = w0*py + w1*cy + w2*ry;
        float az = w0*pz + w1*cz + w2*rz;
        float nm = sqa(ax*ax + ay*ay + az*az) + EPSF;
        float scl = (sG[o]*(nm - sM[o])*sR[o] + sB[o]) * rcpa(nm);
        ax *= scl; ay *= scl; az *= scl;
        float u0 = sWd[3*o], u1 = sWd[3*o+1], u2 = sWd[3*o+2];
        float dx = u0*px + u1*cx + u2*rx;
        float dy = u0*py + u1*cy + u2*ry;
        float dz = u0*pz + u1*cz + u2*rz;
        float dot = ax*dx + ay*dy + az*dz;
        float dsq = dx*dx + dy*dy + dz*dz;
        float t = dot * rcpa(dsq + EPSF);
        float ex, ey, ez;
        if (dot >= 0.f) { ex = ax; ey = ay; ez = az; }
        else { ex = ax - t*dx; ey = ay - t*dy; ez = az - t*dz; }
        ex = 0.2f*ax + 0.8f*ex; ey = 0.2f*ay + 0.8f*ey; ez = 0.2f*az + 0.8f*ez;
        s0[o] = sqa(ex*ex + ey*ey + ez*ez);
    }
    #pragma unroll
    for (int c = 0; c < 8; c++) {
        float v = 0.f;
        #pragma unroll
        for (int o = 0; o < 16; o++) v += sW1[c*16+o] * s0[o];
        g_s1[c*NK + idx] = v;
        float s = v, q = v*v;
        #pragma unroll
        for (int m = 16; m; m >>= 1) {
            s += __shfl_xor_sync(0xffffffffu, s, m);
            q += __shfl_xor_sync(0xffffffffu, q, m);
        }
        if ((tid & 31) == 0) { atomicAdd(&sacc[c], s); atomicAdd(&sacc[8+c], q); }
    }
    __syncthreads();
    if (tid < 16) atomicAdd(&g_stat2[tid], sacc[tid]);
}

// ---------------- score pass 3 ----------------
__global__ void k_score3(const float* __restrict__ bn1g, const float* __restrict__ bn1b,
                         const float* __restrict__ W2, const float* __restrict__ b2)
{
    __shared__ float sM[8], sR[8], sG[8], sB[8], sW[64], sb[8];
    int tid = threadIdx.x;
    if (tid < 8) {
        float m = g_stat2[tid] * 1.25e-5f;
        float v = g_stat2[8+tid] * 1.25e-5f - m*m;
        sM[tid] = m; sR[tid] = rsqa(v + BNEPS);
        sG[tid] = bn1g[tid]; sB[tid] = bn1b[tid]; sb[tid] = b2[tid];
    }
    if (tid < 64) sW[tid] = W2[tid];
    __syncthreads();
    int idx = blockIdx.x * 128 + tid;
    float s[8];
    #pragma unroll
    for (int c = 0; c < 8; c++) {
        float v = g_s1[c*NK + idx];
        v = sG[c]*(v - sM[c])*sR[c] + sB[c];
        s[c] = v > 0.f ? v : 0.f;
    }
    float t[8]; float mx = -1e30f;
    #pragma unroll
    for (int c3 = 0; c3 < 8; c3++) {
        float v = sb[c3];
        #pragma unroll
        for (int c = 0; c < 8; c++) v += sW[c3*8+c] * s[c];
        t[c3] = v; mx = fmaxf(mx, v);
    }
    float sum = 0.f;
    #pragma unroll
    for (int c3 = 0; c3 < 8; c3++) { t[c3] = __expf(t[c3]-mx); sum += t[c3]; }
    float inv = rcpa(sum);
    #pragma unroll
    for (int c3 = 0; c3 < 8; c3++) g_scw[c3*NK + idx] = t[c3]*inv;
}

// ---------------- tensor-core GEMM (fp16, K=128, cp.async pipelined) ----------------
__global__ void __launch_bounds__(256,2) k_gemmt(
    const int* __restrict__ rowmap, int wsel, int csel, int M, int Nc)
{
    const __half* Ap = g_Apack;
    const __half* Wt = (wsel == 0) ? g_WtG : g_WtBI;

    __shared__ __align__(16) __half As[2][128][40];
    __shared__ __align__(16) __half Bs[2][128][40];

    int tid = threadIdx.x;
    int bm = blockIdx.x * 128, bn = blockIdx.y * 128;

    int lr = tid >> 2;
    int lc8 = (tid & 3) * 8;

    const __half *pa0, *pa1; bool gd0, gd1;
    {
        int r = bm + lr; gd0 = r < M;
        int src = gd0 ? r : 0;
        if (rowmap && gd0) { int grp = r/3, d = r - grp*3; src = rowmap[grp*16]*3 + d; }
        pa0 = Ap + (size_t)src*128;
        r = bm + lr + 64; gd1 = r < M;
        src = gd1 ? r : 0;
        if (rowmap && gd1) { int grp = r/3, d = r - grp*3; src = rowmap[grp*16]*3 + d; }
        pa1 = Ap + (size_t)src*128;
    }
    const __half* pb0 = Wt + (size_t)(bn + lr)*128 + lc8;
    const __half* pb1 = Wt + (size_t)(bn + lr + 64)*128 + lc8;

    int lane = tid & 31, wid = tid >> 5;
    int warp_m = (wid & 1) * 64;
    int warp_n = (wid >> 1) * 32;

    float acc[4][4][4] = {};

    auto issue = [&](int kt, int b){
        int ktb = kt * 32;
        cp16p(&As[b][lr][lc8],    pa0 + ktb + lc8, gd0);
        cp16p(&As[b][lr+64][lc8], pa1 + ktb + lc8, gd1);
        cp16(&Bs[b][lr][lc8],    pb0 + ktb);
        cp16(&Bs[b][lr+64][lc8], pb1 + ktb);
        asm volatile("cp.async.commit_group;" ::: "memory");
    };

    issue(0, 0);
    asm volatile("cp.async.wait_group 0;" ::: "memory");
    __syncthreads();
    int buf = 0;

    #pragma unroll 1
    for (int kt = 0; kt < 4; kt++) {
        if (kt + 1 < 4) issue(kt + 1, buf ^ 1);
        #pragma unroll
        for (int ks = 0; ks < 32; ks += 16) {
            u32 af[4][4], bf2[4][2];
            #pragma unroll
            for (int mt = 0; mt < 4; mt++) {
                int row = warp_m + mt*16 + (lane & 7) + ((lane >> 3) & 1)*8;
                int col = ks + (lane >> 4)*8;
                u32 sa = (u32)__cvta_generic_to_shared(&As[buf][row][col]);
                asm volatile("ldmatrix.sync.aligned.m8n8.x4.shared.b16 {%0,%1,%2,%3}, [%4];"
                    : "=r"(af[mt][0]), "=r"(af[mt][1]), "=r"(af[mt][2]), "=r"(af[mt][3]) : "r"(sa));
            }
            #pragma unroll
            for (int pr = 0; pr < 2; pr++) {
                int row = warp_n + pr*16 + (lane & 7) + ((lane >> 4) & 1)*8;
                int col = ks + ((lane >> 3) & 1)*8;
                u32 sb = (u32)__cvta_generic_to_shared(&Bs[buf][row][col]);
                asm volatile("ldmatrix.sync.aligned.m8n8.x4.shared.b16 {%0,%1,%2,%3}, [%4];"
                    : "=r"(bf2[pr*2][0]), "=r"(bf2[pr*2][1]),
                      "=r"(bf2[pr*2+1][0]), "=r"(bf2[pr*2+1][1]) : "r"(sb));
            }
            #pragma unroll
            for (int mt = 0; mt < 4; mt++)
                #pragma unroll
                for (int nt = 0; nt < 4; nt++) {
                    asm volatile(
                        "mma.sync.aligned.m16n8k16.row.col.f32.f16.f16.f32 "
                        "{%0,%1,%2,%3}, {%4,%5,%6,%7}, {%8,%9}, {%0,%1,%2,%3};"
                        : "+f"(acc[mt][nt][0]), "+f"(acc[mt][nt][1]),
                          "+f"(acc[mt][nt][2]), "+f"(acc[mt][nt][3])
                        : "r"(af[mt][0]), "r"(af[mt][1]), "r"(af[mt][2]), "r"(af[mt][3]),
                          "r"(bf2[nt][0]), "r"(bf2[nt][1]));
                }
        }
        if (kt + 1 < 4) {
            asm volatile("cp.async.wait_group 0;" ::: "memory");
            __syncthreads();
            buf ^= 1;
        }
    }

    int g = lane >> 2, tig = lane & 3;
    #pragma unroll
    for (int mt = 0; mt < 4; mt++) {
        #pragma unroll
        for (int nt = 0; nt < 4; nt++) {
            int r0 = bm + warp_m + mt*16 + g;
            int cc = bn + warp_n + nt*8 + 2*tig;
            int r1 = r0 + 8;
            if (csel == 0) {
                if (r0 < M)
                    *(__half2*)&g_Gh[(size_t)r0*Nc + cc] = __floats2half2_rn(acc[mt][nt][0], acc[mt][nt][1]);
                if (r1 < M)
                    *(__half2*)&g_Gh[(size_t)r1*Nc + cc] = __floats2half2_rn(acc[mt][nt][2], acc[mt][nt][3]);
            } else {
                if (r0 < M)
                    *(float2*)&g_BqId[(size_t)r0*Nc + cc] = make_float2(acc[mt][nt][0], acc[mt][nt][1]);
                if (r1 < M)
                    *(float2*)&g_BqId[(size_t)r1*Nc + cc] = make_float2(acc[mt][nt][2], acc[mt][nt][3]);
            }
        }
    }
}

// ---------------- FFMA2 SGEMM (pd3 only; bmOff = block-row offset) ----------------
#define GBM 128
#define GBN 128
#define GBK 16
__global__ void __launch_bounds__(256,2) k_gemm2(int bmOff, int M, int Nc, int Kd)
{
    const float* A = g_f2;
    const float* W = g_W23;
    float* C = g_pd3;

    __shared__ __align__(16) float As[2][GBK][GBM+4];
    __shared__ __align__(16) float Ws[2][GBK][GBN];
    int tid = threadIdx.x;
    int bm = (blockIdx.x + bmOff) * GBM, bn = blockIdx.y * GBN;

    int ar = tid >> 2, ac = (tid & 3) * 4;
    const float *pa0, *pa1; bool gd0, gd1;
    {
        int r = bm + ar; gd0 = r < M;
        pa0 = A + (size_t)(gd0 ? r : 0)*Kd + ac;
        r = bm + ar + 64; gd1 = r < M;
        pa1 = A + (size_t)(gd1 ? r : 0)*Kd + ac;
    }
    int wr = tid >> 4, wc = (tid & 15) * 8;
    const float* pw = W + (size_t)wr*Nc + bn + wc;

    int tr = tid >> 4, tc = tid & 15;
    u64 acc2[8][4] = {};
    int nk = Kd / GBK;
    const float4 f4z = make_float4(0.f,0.f,0.f,0.f);

    float4 va0 = gd0 ? *(const float4*)(pa0) : f4z;
    float4 va1 = gd1 ? *(const float4*)(pa1) : f4z;
    float4 vb0 = *(const float4*)(pw);
    float4 vb1 = *(const float4*)(pw + 4);
    As[0][ac+0][ar] = va0.x; As[0][ac+1][ar] = va0.y; As[0][ac+2][ar] = va0.z; As[0][ac+3][ar] = va0.w;
    As[0][ac+0][ar+64] = va1.x; As[0][ac+1][ar+64] = va1.y; As[0][ac+2][ar+64] = va1.z; As[0][ac+3][ar+64] = va1.w;
    *(float4*)&Ws[0][wr][wc] = vb0; *(float4*)&Ws[0][wr][wc+4] = vb1;
    __syncthreads();
    int buf = 0;

    for (int kt = 0; kt < nk; kt++) {
        if (kt + 1 < nk) {
            int k0 = (kt+1) * GBK;
            va0 = gd0 ? *(const float4*)(pa0 + k0) : f4z;
            va1 = gd1 ? *(const float4*)(pa1 + k0) : f4z;
            vb0 = *(const float4*)(pw + (size_t)k0*Nc);
            vb1 = *(const float4*)(pw + (size_t)k0*Nc + 4);
        }
        #pragma unroll
        for (int kk = 0; kk < GBK; kk++) {
            float4 a0 = *(const float4*)&As[buf][kk][tr*8];
            float4 a1 = *(const float4*)&As[buf][kk][tr*8+4];
            ulonglong2 B0 = *(const ulonglong2*)&Ws[buf][kk][tc*8];
            ulonglong2 B1 = *(const ulonglong2*)&Ws[buf][kk][tc*8+4];
            float aa[8] = {a0.x,a0.y,a0.z,a0.w,a1.x,a1.y,a1.z,a1.w};
            #pragma unroll
            for (int ii = 0; ii < 8; ii++) {
                u64 ad = dup2(aa[ii]);
                fma2(acc2[ii][0], ad, B0.x);
                fma2(acc2[ii][1], ad, B0.y);
                fma2(acc2[ii][2], ad, B1.x);
                fma2(acc2[ii][3], ad, B1.y);
            }
        }
        if (kt + 1 < nk) {
            int nb = buf ^ 1;
            As[nb][ac+0][ar] = va0.x; As[nb][ac+1][ar] = va0.y; As[nb][ac+2][ar] = va0.z; As[nb][ac+3][ar] = va0.w;
            As[nb][ac+0][ar+64] = va1.x; As[nb][ac+1][ar+64] = va1.y; As[nb][ac+2][ar+64] = va1.z; As[nb][ac+3][ar+64] = va1.w;
            *(float4*)&Ws[nb][wr][wc] = vb0; *(float4*)&Ws[nb][wr][wc+4] = vb1;
            __syncthreads();
            buf = nb;
        }
    }
    #pragma unroll
    for (int i = 0; i < 8; i++) {
        int r = bm + tr*8 + i;
        if (r < M) {
            float* cp = &C[(size_t)r*Nc + bn + tc*8];
            *(ulonglong2*)cp     = make_ulonglong2(acc2[i][0], acc2[i][1]);
            *(ulonglong2*)(cp+4) = make_ulonglong2(acc2[i][2], acc2[i][3]);
        }
    }
}

// ---------------- combine + mid fused (nOff = block offset) ----------------
__global__ void __launch_bounds__(256) k_combine(const float* __restrict__ wb,
    const float* __restrict__ q_pts, const float* __restrict__ s_pts,
    const int* __restrict__ nbr, const float* __restrict__ Wr, int nOff)
{
    __shared__ float sc[4][16][8];
    __shared__ int   jl[4][16];
    __shared__ float ptsh[4][16][3];
    __shared__ float Wsh[64][65];
    __shared__ float fsh[4][3][64];
    int tid = threadIdx.x;
    int base = (blockIdx.x + nOff) * 4;
    {
        int e = tid;
        int nl = e >> 6, rem = e & 63, k = rem >> 2, g0 = (rem & 3) * 2;
        int idx = (base+nl)*16 + k;
        sc[nl][k][g0]   = g_scw[g0*NK + idx];
        sc[nl][k][g0+1] = g_scw[(g0+1)*NK + idx];
    }
    if (tid < 64) jl[tid>>4][tid&15] = nbr[(base + (tid>>4))*16 + (tid&15)];
    if (tid < 192) {
        int nl = tid/48, rem = tid - nl*48, k = rem/3, d = rem - k*3;
        int n = base + nl;
        ptsh[nl][k][d] = s_pts[nbr[n*16+k]*3 + d] - q_pts[n*3 + d];
    }
    for (int e = tid; e < 4096; e += 256) {
        int o = e >> 6, hh = e & 63;
        Wsh[hh][o] = Wr[e];
    }
    int nl = tid >> 6, h = tid & 63;
    int n = base + nl;
    float bq[3][8], w2[8];
    #pragma unroll
    for (int g = 0; g < 8; g++) w2[g] = wb[256*512 + g*64 + h];
    #pragma unroll
    for (int d = 0; d < 3; d++) {
        float4 b0 = *(const float4*)&g_BqId[(size_t)(n*3+d)*640 + h*8];
        float4 b1 = *(const float4*)&g_BqId[(size_t)(n*3+d)*640 + h*8 + 4];
        bq[d][0]=b0.x; bq[d][1]=b0.y; bq[d][2]=b0.z; bq[d][3]=b0.w;
        bq[d][4]=b1.x; bq[d][5]=b1.y; bq[d][6]=b1.z; bq[d][7]=b1.w;
    }
    __syncthreads();
    float acc0 = 0.f, acc1 = 0.f, acc2 = 0.f;
    for (int k = 0; k < 16; k++) {
        int j = jl[nl][k];
        float s[8];
        #pragma unroll
        for (int g = 0; g < 8; g++) s[g] = sc[nl][k][g];
        float scw2 = 0.f;
        #pragma unroll
        for (int g = 0; g < 8; g++) scw2 += s[g]*w2[g];
        float v[3];
        #pragma unroll
        for (int d = 0; d < 3; d++) {
            uint4 gv = *(const uint4*)&g_Gh[(size_t)(j*3+d)*512 + h*8];
            __half2* gh = (__half2*)&gv;
            float2 q0 = __half22float2(gh[0]);
            float2 q1 = __half22float2(gh[1]);
            float2 q2 = __half22float2(gh[2]);
            float2 q3 = __half22float2(gh[3]);
            float t = s[0]*(q0.x - bq[d][0]) + s[1]*(q0.y - bq[d][1])
                    + s[2]*(q1.x - bq[d][2]) + s[3]*(q1.y - bq[d][3])
                    + s[4]*(q2.x - bq[d][4]) + s[5]*(q2.y - bq[d][5])
                    + s[6]*(q3.x - bq[d][6]) + s[7]*(q3.y - bq[d][7]);
            v[d] = t + ptsh[nl][k][d]*scw2;
        }
        float nrm2 = v[0]*v[0] + v[1]*v[1] + v[2]*v[2];
        float inv = rsqa(fmaxf(nrm2, 1e-24f));
        acc0 += v[0]*inv; acc1 += v[1]*inv; acc2 += v[2]*inv;
    }
    fsh[nl][0][h] = acc0 * 0.0625f;
    fsh[nl][1][h] = acc1 * 0.0625f;
    fsh[nl][2][h] = acc2 * 0.0625f;
    __syncthreads();
    int o = h;
    float p[3], d2[3];
    #pragma unroll
    for (int d = 0; d < 3; d++) {
        p[d] = fsh[nl][d][o];
        float t = 0.f;
        #pragma unroll 8
        for (int hh = 0; hh < 64; hh++) t += fsh[nl][d][hh]*Wsh[hh][o];
        d2[d] = t;
    }
    float dot = p[0]*d2[0] + p[1]*d2[1] + p[2]*d2[2];
    float dsq = d2[0]*d2[0] + d2[1]*d2[1] + d2[2]*d2[2];
    float t2 = dot * rcpa(dsq + EPSF);
    #pragma unroll
    for (int d = 0; d < 3; d++) {
        float s = (dot >= 0.f) ? p[d] : p[d] - t2*d2[d];
        g_f2[(n*3+d)*64 + o] = 0.2f*p[d] + 0.8f*s;
    }
}

// ---------------- stats of ||p3|| (grid-strided) ----------------
__global__ void k_stat3b()
{
    int o = threadIdx.x;
    float s = 0.f, ss = 0.f;
    for (int n = blockIdx.x; n < 5000; n += gridDim.x) {
        float a = g_pd3[(size_t)(n*3+0)*256 + o];
        float b = g_pd3[(size_t)(n*3+1)*256 + o];
        float c = g_pd3[(size_t)(n*3+2)*256 + o];
        float nm = sqa(a*a + b*b + c*c) + EPSF;
        s += nm; ss += nm*nm;
    }
    atomicAdd(&g_stat3[o], s);
    atomicAdd(&g_stat3[128+o], ss);
}

// ---------------- final: 2 n per block ----------------
__global__ void k_tail2(const float* __restrict__ ung, const float* __restrict__ unb,
                        float* __restrict__ out)
{
    int tid = threadIdx.x;
    int n = blockIdx.x * 2 + (tid >> 7);
    int o = tid & 127;
    float m = g_stat3[o] * 2e-4f;
    float v = g_stat3[128+o] * 2e-4f - m*m;
    float rstd = rsqa(v + BNEPS);
    float a0 = g_pd3[(size_t)(n*3+0)*256 + o];
    float a1 = g_pd3[(size_t)(n*3+1)*256 + o];
    float a2 = g_pd3[(size_t)(n*3+2)*256 + o];
    float nm = sqa(a0*a0 + a1*a1 + a2*a2) + EPSF;
    float scl = (ung[o]*(nm - m)*rstd + unb[o]) * rcpa(nm);
    a0 *= scl; a1 *= scl; a2 *= scl;
    float e0 = g_pd3[(size_t)(n*3+0)*256 + 128 + o];
    float e1 = g_pd3[(size_t)(n*3+1)*256 + 128 + o];
    float e2 = g_pd3[(size_t)(n*3+2)*256 + 128 + o];
    float dot = a0*e0 + a1*e1 + a2*e2;
    float dsq = e0*e0 + e1*e1 + e2*e2;
    float t = dot * rcpa(dsq + EPSF);
    float s0, s1, s2;
    if (dot >= 0.f) { s0 = a0; s1 = a1; s2 = a2; }
    else { s0 = a0 - t*e0; s1 = a1 - t*e1; s2 = a2 - t*e2; }
    float r0 = 0.2f*a0 + 0.8f*s0;
    float r1 = 0.2f*a1 + 0.8f*s1;
    float r2 = 0.2f*a2 + 0.8f*s2;
    int b = (n*128+o)*3;
    out[b]   = r0 + g_BqId[(size_t)(n*3+0)*640 + 512 + o];
    out[b+1] = r1 + g_BqId[(size_t)(n*3+1)*640 + 512 + o];
    out[b+2] = r2 + g_BqId[(size_t)(n*3+2)*640 + 512 + o];
}

// ---------------- launch (capture-safe fork/join + pipelined tail) ----------------
extern "C" void kernel_launch(void* const* d_in, const int* in_sizes, int n_in,
                              void* d_out, int out_size)
{
    const float* q_pts  = (const float*)d_in[0];
    const float* s_pts  = (const float*)d_in[1];
    const float* s_feats= (const float*)d_in[2];
    const int*   nbr    = (const int*)  d_in[3];
    const float* Wf     = (const float*)d_in[4];
    const float* Wd     = (const float*)d_in[5];
    const float* vng    = (const float*)d_in[6];
    const float* vnb    = (const float*)d_in[7];
    const float* W1     = (const float*)d_in[8];
    const float* bn1g   = (const float*)d_in[9];
    const float* bn1b   = (const float*)d_in[10];
    const float* W2     = (const float*)d_in[11];
    const float* b2     = (const float*)d_in[12];
    const float* wb     = (const float*)d_in[13];
    const float* Wsc    = (const float*)d_in[14];
    const float* Wrelu  = (const float*)d_in[15];
    const float* unWf   = (const float*)d_in[16];
    const float* unWd   = (const float*)d_in[17];
    const float* ung    = (const float*)d_in[18];
    const float* unb    = (const float*)d_in[19];
    float* out = (float*)d_out;

    static cudaStream_t sB = nullptr, sC = nullptr;
    static cudaEvent_t evF = nullptr, evS = nullptr, evA = nullptr, evW = nullptr,
                       evB = nullptr, evG = nullptr, evCB = nullptr;
    if (!sB) {
        cudaStreamCreateWithFlags(&sB, cudaStreamNonBlocking);
        cudaStreamCreateWithFlags(&sC, cudaStreamNonBlocking);
        cudaEventCreateWithFlags(&evF, cudaEventDisableTiming);
        cudaEventCreateWithFlags(&evS, cudaEventDisableTiming);
        cudaEventCreateWithFlags(&evA, cudaEventDisableTiming);
        cudaEventCreateWithFlags(&evW, cudaEventDisableTiming);
        cudaEventCreateWithFlags(&evB, cudaEventDisableTiming);
        cudaEventCreateWithFlags(&evG, cudaEventDisableTiming);
        cudaEventCreateWithFlags(&evCB, cudaEventDisableTiming);
    }

    // origin stream: init, then fork
    k_init<<<1, 256>>>();
    cudaEventRecord(evF, 0);

    // sC forks from origin: prepW concurrent with prepA
    cudaStreamWaitEvent(sC, evF, 0);
    k_prepW<<<640, 256, 0, sC>>>(wb, Wsc, unWf, unWd);
    cudaEventRecord(evW, sC);

    k_prepA<<<1250, 256>>>(s_feats);
    cudaEventRecord(evA, 0);

    // G GEMM on origin (needs prepA + prepW)
    cudaStreamWaitEvent(0, evW, 0);
    k_gemmt<<<dim3(235, 4), 256>>>(nullptr, 0, 0, 30000, 512);     // launch 4 (profiled)
    cudaEventRecord(evG, 0);

    // BqId GEMM on sC (after prepW same-stream; needs prepA via evA)
    cudaStreamWaitEvent(sC, evA, 0);
    k_gemmt<<<dim3(118, 5), 256, 0, sC>>>(nbr, 1, 1, 15000, 640);
    cudaEventRecord(evB, sC);

    // sB forks from origin: score chain
    cudaStreamWaitEvent(sB, evF, 0);
    k_score1<<<625, 128, 0, sB>>>(q_pts, s_pts, nbr, Wf);
    k_score2<<<625, 128, 0, sB>>>(q_pts, s_pts, nbr, Wf, Wd, vng, vnb, W1);
    k_score3<<<625, 128, 0, sB>>>(bn1g, bn1b, W2, b2);
    cudaEventRecord(evS, sB);

    // origin: combine_A (n 0..2499) after full join
    cudaStreamWaitEvent(0, evS, 0);
    cudaStreamWaitEvent(0, evB, 0);
    k_combine<<<625, 256>>>(wb, q_pts, s_pts, nbr, Wrelu, 0);
    // gemm2_A: rows 0..7423 (blocks 0..57) — depends only on combine_A
    k_gemm2<<<dim3(58, 2), 256>>>(0, 15000, 256, 64);

    // sC: combine_B (n 2500..4999), concurrent with gemm2_A
    cudaStreamWaitEvent(sC, evS, 0);
    cudaStreamWaitEvent(sC, evG, 0);
    k_combine<<<625, 256, 0, sC>>>(wb, q_pts, s_pts, nbr, Wrelu, 625);
    cudaEventRecord(evCB, sC);

    // origin: gemm2_B (rows 7424..14999) after combine_B
    cudaStreamWaitEvent(0, evCB, 0);
    k_gemm2<<<dim3(60, 2), 256>>>(58, 15000, 256, 64);

    k_stat3b<<<125, 128>>>();
    k_tail2<<<2500, 256>>>(ung, unb, out);
}